// round 1
// baseline (speedup 1.0000x reference)
#include <cuda_runtime.h>

#define DI __device__ __forceinline__

// ---------------- static scratch (no allocs allowed) ----------------
__device__ float g_bufA[67108864];          // 256 MiB: up to [16,256,16384]
__device__ float g_bufB[67108864];          // 256 MiB
__device__ float g_z[16 * 64 * 2048];       // encoder latent
__device__ float g_q[16 * 64 * 2048];       // quantized latent
__device__ float g_wt[9 * 768 * 256];       // repacked weights, 9 slots
__device__ float g_cbT[64 * 512];           // codebook transposed [k][code]
__device__ float g_cnh[512];                // 0.5*||c||^2

DI float4 ldf4s(const float* p) { return *reinterpret_cast<const float4*>(p); }

DI void rank1(float a[4][4], float4 w, float4 x) {
    float wv[4] = {w.x, w.y, w.z, w.w};
    float xv[4] = {x.x, x.y, x.z, x.w};
#pragma unroll
    for (int i = 0; i < 4; i++)
#pragma unroll
        for (int j = 0; j < 4; j++) a[i][j] = fmaf(wv[i], xv[j], a[i][j]);
}

// ---------------- weight repack: w[oc][ic][k] -> wt[(ic*3+k)][oc] ----------------
__global__ void repack_w_kernel(const float* __restrict__ w, float* __restrict__ wt,
                                int OC, int IC) {
    int i = blockIdx.x * 256 + threadIdx.x;
    int n = OC * IC * 3;
    if (i < n) {
        int oc = i / (IC * 3);
        int r = i - oc * IC * 3;
        wt[r * OC + oc] = w[i];
    }
}

// ---------------- codebook prep ----------------
__global__ void cb_prep_kernel(const float* __restrict__ cb, float* __restrict__ cbT,
                               float* __restrict__ cnh) {
    int c = threadIdx.x;  // 512 threads
    float s = 0.f;
    for (int k = 0; k < 64; k++) {
        float v = cb[c * 64 + k];
        cbT[k * 512 + c] = v;
        s += v * v;
    }
    cnh[c] = 0.5f * s;
}

// ---------------- encoder layer 1: in_ch=1, stride 2, relu ----------------
__global__ void e1_kernel(const float* __restrict__ x, const float* __restrict__ w,
                          const float* __restrict__ bias, float* __restrict__ out) {
    int idx = blockIdx.x * blockDim.x + threadIdx.x;  // 16*256*4096 total
    int t4 = idx & 4095;
    int oc = (idx >> 12) & 255;
    int b = idx >> 20;
    int t = t4 * 4;
    const float* xr = x + (size_t)b * 32768;
    float w0 = w[oc * 3], w1 = w[oc * 3 + 1], w2 = w[oc * 3 + 2], bv = bias[oc];
    float v[4];
#pragma unroll
    for (int j = 0; j < 4; j++) {
        int p = 2 * (t + j);
        float xm = (p - 1 >= 0) ? xr[p - 1] : 0.f;
        float r = bv + w0 * xm + w1 * xr[p] + w2 * xr[p + 1];
        v[j] = fmaxf(r, 0.f);
    }
    float4 o4 = make_float4(v[0], v[1], v[2], v[3]);
    *reinterpret_cast<float4*>(out + (size_t)(b * 256 + oc) * 16384 + t) = o4;
}

// ---------------- stride-2 conv, IC=OC=256 ----------------
template <bool RELU>
__global__ void __launch_bounds__(256)
conv_s2_kernel(const float* __restrict__ x, const float* __restrict__ wt,
               const float* __restrict__ bias, float* __restrict__ out,
               int Tin, int Tout) {
    __shared__ __align__(16) float ws[48 * 128];
    __shared__ __align__(16) float xE[16 * 128];
    __shared__ __align__(16) float xO[16 * 132];

    const int t0 = blockIdx.x * 128;
    const int oc0 = blockIdx.y * 128;
    const int b = blockIdx.z;
    const int tid = threadIdx.x;
    const float* xb = x + (size_t)b * 256 * Tin;

    const int oc_sub = tid & 15, t_sub = tid >> 4;
    const int ocq0 = oc_sub * 4, tq0 = t_sub * 4;

    float acc[2][2][4][4];
#pragma unroll
    for (int a = 0; a < 2; a++)
#pragma unroll
        for (int q = 0; q < 2; q++)
#pragma unroll
            for (int i = 0; i < 4; i++)
#pragma unroll
                for (int j = 0; j < 4; j++) acc[a][q][i][j] = 0.f;

    for (int ic0 = 0; ic0 < 256; ic0 += 16) {
        for (int i = tid * 4; i < 48 * 128; i += 256 * 4) {
            int row = i >> 7, col = i & 127;
            *reinterpret_cast<float4*>(&ws[i]) =
                ldf4s(&wt[(size_t)(ic0 * 3 + row) * 256 + oc0 + col]);
        }
        for (int i = tid; i < 16 * 257; i += 256) {
            int icl = i / 257, r = i - icl * 257;
            int gp = 2 * t0 - 1 + r;
            float v = (gp >= 0) ? xb[(size_t)(ic0 + icl) * Tin + gp] : 0.f;
            if (r & 1) xE[icl * 128 + ((r - 1) >> 1)] = v;   // even global pos
            else       xO[icl * 132 + (r >> 1)] = v;         // odd global pos
        }
        __syncthreads();
#pragma unroll 2
        for (int icl = 0; icl < 16; icl++) {
            const float* wr = &ws[icl * 3 * 128];
            float4 w00 = ldf4s(wr + ocq0),           w10 = ldf4s(wr + ocq0 + 64);
            float4 w01 = ldf4s(wr + 128 + ocq0),     w11 = ldf4s(wr + 128 + ocq0 + 64);
            float4 w02 = ldf4s(wr + 256 + ocq0),     w12 = ldf4s(wr + 256 + ocq0 + 64);
            const float* xe = &xE[icl * 128];
            const float* xo = &xO[icl * 132];
            float4 xe0 = ldf4s(xe + tq0), xe1 = ldf4s(xe + tq0 + 64);
            float4 xo0 = ldf4s(xo + tq0), xo1 = ldf4s(xo + tq0 + 64);
            float xo0h = xo[tq0 + 4], xo1h = xo[tq0 + 68];
            float4 xs0 = make_float4(xo0.y, xo0.z, xo0.w, xo0h);
            float4 xs1 = make_float4(xo1.y, xo1.z, xo1.w, xo1h);
            rank1(acc[0][0], w00, xo0); rank1(acc[0][1], w00, xo1);   // k=0
            rank1(acc[1][0], w10, xo0); rank1(acc[1][1], w10, xo1);
            rank1(acc[0][0], w01, xe0); rank1(acc[0][1], w01, xe1);   // k=1
            rank1(acc[1][0], w11, xe0); rank1(acc[1][1], w11, xe1);
            rank1(acc[0][0], w02, xs0); rank1(acc[0][1], w02, xs1);   // k=2
            rank1(acc[1][0], w12, xs0); rank1(acc[1][1], w12, xs1);
        }
        __syncthreads();
    }
#pragma unroll
    for (int o = 0; o < 2; o++)
#pragma unroll
        for (int i = 0; i < 4; i++) {
            int oc = oc0 + ocq0 + o * 64 + i;
            float bv = bias[oc];
            float* orow = out + (size_t)(b * 256 + oc) * Tout + t0;
#pragma unroll
            for (int q = 0; q < 2; q++) {
                float4 v;
                v.x = acc[o][q][i][0] + bv; v.y = acc[o][q][i][1] + bv;
                v.z = acc[o][q][i][2] + bv; v.w = acc[o][q][i][3] + bv;
                if (RELU) {
                    v.x = fmaxf(v.x, 0.f); v.y = fmaxf(v.y, 0.f);
                    v.z = fmaxf(v.z, 0.f); v.w = fmaxf(v.w, 0.f);
                }
                *reinterpret_cast<float4*>(orow + q * 64 + tq0) = v;
            }
        }
}

// ---------------- stride-1 conv, generic IC/OC ----------------
template <int BO, bool RELU>
__global__ void conv_s1_kernel(const float* __restrict__ x, const float* __restrict__ wt,
                               const float* __restrict__ bias, float* __restrict__ out,
                               int T, int IC, int OC) {
    const int THREADS = BO * 2;
    __shared__ __align__(16) float ws[48 * BO];
    __shared__ __align__(16) float xs[16 * 132];
    const int t0 = blockIdx.x * 128;
    const int oc0 = blockIdx.y * BO;
    const int b = blockIdx.z;
    const int tid = threadIdx.x;
    const int OCS = BO / 8;
    const int oc_sub = tid % OCS, t_sub = tid / OCS;
    const int ocq0 = oc_sub * 4, tq0 = t_sub * 4;
    const float* xb = x + (size_t)b * IC * T;

    float acc[2][2][4][4];
#pragma unroll
    for (int a = 0; a < 2; a++)
#pragma unroll
        for (int q = 0; q < 2; q++)
#pragma unroll
            for (int i = 0; i < 4; i++)
#pragma unroll
                for (int j = 0; j < 4; j++) acc[a][q][i][j] = 0.f;

    for (int ic0 = 0; ic0 < IC; ic0 += 16) {
        for (int i = tid * 4; i < 48 * BO; i += THREADS * 4) {
            int row = i / BO, col = i % BO;
            *reinterpret_cast<float4*>(&ws[i]) =
                ldf4s(&wt[(size_t)(ic0 * 3 + row) * OC + oc0 + col]);
        }
        for (int i = tid; i < 16 * 130; i += THREADS) {
            int icl = i / 130, r = i - icl * 130;
            int gp = t0 - 1 + r;
            float v = (gp >= 0 && gp < T) ? xb[(size_t)(ic0 + icl) * T + gp] : 0.f;
            xs[icl * 132 + r] = v;
        }
        __syncthreads();
#pragma unroll 2
        for (int icl = 0; icl < 16; icl++) {
            const float* wr = &ws[icl * 3 * BO];
            float4 w00 = ldf4s(wr + ocq0),            w10 = ldf4s(wr + ocq0 + BO / 2);
            float4 w01 = ldf4s(wr + BO + ocq0),       w11 = ldf4s(wr + BO + ocq0 + BO / 2);
            float4 w02 = ldf4s(wr + 2 * BO + ocq0),   w12 = ldf4s(wr + 2 * BO + ocq0 + BO / 2);
            const float* xr = &xs[icl * 132];
            float4 a0 = ldf4s(xr + tq0);
            float h0a = xr[tq0 + 4], h0b = xr[tq0 + 5];
            float4 a1 = ldf4s(xr + tq0 + 64);
            float h1a = xr[tq0 + 68], h1b = xr[tq0 + 69];
            float4 x00 = a0;
            float4 x01 = make_float4(a0.y, a0.z, a0.w, h0a);
            float4 x02 = make_float4(a0.z, a0.w, h0a, h0b);
            float4 x10 = a1;
            float4 x11 = make_float4(a1.y, a1.z, a1.w, h1a);
            float4 x12 = make_float4(a1.z, a1.w, h1a, h1b);
            rank1(acc[0][0], w00, x00); rank1(acc[0][1], w00, x10);
            rank1(acc[1][0], w10, x00); rank1(acc[1][1], w10, x10);
            rank1(acc[0][0], w01, x01); rank1(acc[0][1], w01, x11);
            rank1(acc[1][0], w11, x01); rank1(acc[1][1], w11, x11);
            rank1(acc[0][0], w02, x02); rank1(acc[0][1], w02, x12);
            rank1(acc[1][0], w12, x02); rank1(acc[1][1], w12, x12);
        }
        __syncthreads();
    }
#pragma unroll
    for (int o = 0; o < 2; o++)
#pragma unroll
        for (int i = 0; i < 4; i++) {
            int oc = oc0 + ocq0 + o * (BO / 2) + i;
            float bv = bias[oc];
            float* orow = out + (size_t)(b * OC + oc) * T + t0;
#pragma unroll
            for (int q = 0; q < 2; q++) {
                float4 v;
                v.x = acc[o][q][i][0] + bv; v.y = acc[o][q][i][1] + bv;
                v.z = acc[o][q][i][2] + bv; v.w = acc[o][q][i][3] + bv;
                if (RELU) {
                    v.x = fmaxf(v.x, 0.f); v.y = fmaxf(v.y, 0.f);
                    v.z = fmaxf(v.z, 0.f); v.w = fmaxf(v.w, 0.f);
                }
                *reinterpret_cast<float4*>(orow + q * 64 + tq0) = v;
            }
        }
}

// ---------------- transposed conv (stride 2 upsample), IC=OC=256 ----------------
// out[2m]   = sum_i x[i][m]   * w[o][i][1]
// out[2m+1] = sum_i x[i][m] * w[o][i][0] + x[i][m+1] * w[o][i][2]
template <bool RELU>
__global__ void __launch_bounds__(256)
convT_kernel(const float* __restrict__ x, const float* __restrict__ wt,
             const float* __restrict__ bias, float* __restrict__ out,
             int Tin, int Tout) {
    __shared__ __align__(16) float ws[48 * 128];
    __shared__ __align__(16) float xs[16 * 68];

    const int m0 = blockIdx.x * 64;
    const int oc0 = blockIdx.y * 128;
    const int b = blockIdx.z;
    const int tid = threadIdx.x;
    const float* xb = x + (size_t)b * 256 * Tin;

    const int oc_sub = tid & 15, m_sub = tid >> 4;
    const int ocq0 = oc_sub * 4, mq = m_sub * 4;

    float ae[2][4][4], ao[2][4][4];
#pragma unroll
    for (int o = 0; o < 2; o++)
#pragma unroll
        for (int i = 0; i < 4; i++)
#pragma unroll
            for (int j = 0; j < 4; j++) { ae[o][i][j] = 0.f; ao[o][i][j] = 0.f; }

    for (int ic0 = 0; ic0 < 256; ic0 += 16) {
        for (int i = tid * 4; i < 48 * 128; i += 256 * 4) {
            int row = i >> 7, col = i & 127;
            *reinterpret_cast<float4*>(&ws[i]) =
                ldf4s(&wt[(size_t)(ic0 * 3 + row) * 256 + oc0 + col]);
        }
        for (int i = tid; i < 16 * 65; i += 256) {
            int icl = i / 65, r = i - icl * 65;
            int gp = m0 + r;
            float v = (gp < Tin) ? xb[(size_t)(ic0 + icl) * Tin + gp] : 0.f;
            xs[icl * 68 + r] = v;
        }
        __syncthreads();
#pragma unroll 2
        for (int icl = 0; icl < 16; icl++) {
            const float* wr = &ws[icl * 3 * 128];
            float4 w00 = ldf4s(wr + ocq0),         w10 = ldf4s(wr + ocq0 + 64);
            float4 w01 = ldf4s(wr + 128 + ocq0),   w11 = ldf4s(wr + 128 + ocq0 + 64);
            float4 w02 = ldf4s(wr + 256 + ocq0),   w12 = ldf4s(wr + 256 + ocq0 + 64);
            float4 xv = ldf4s(&xs[icl * 68 + mq]);
            float xh = xs[icl * 68 + mq + 4];
            float4 xsh = make_float4(xv.y, xv.z, xv.w, xh);
            rank1(ae[0], w01, xv); rank1(ae[1], w11, xv);     // even: k=1
            rank1(ao[0], w00, xv); rank1(ao[1], w10, xv);     // odd:  k=0
            rank1(ao[0], w02, xsh); rank1(ao[1], w12, xsh);   // odd:  k=2
        }
        __syncthreads();
    }
#pragma unroll
    for (int o = 0; o < 2; o++)
#pragma unroll
        for (int i = 0; i < 4; i++) {
            int oc = oc0 + ocq0 + o * 64 + i;
            float bv = bias[oc];
            float* base = out + (size_t)(b * 256 + oc) * Tout + 2 * (m0 + mq);
            float4 v0, v1;
            v0.x = ae[o][i][0] + bv; v0.y = ao[o][i][0] + bv;
            v0.z = ae[o][i][1] + bv; v0.w = ao[o][i][1] + bv;
            v1.x = ae[o][i][2] + bv; v1.y = ao[o][i][2] + bv;
            v1.z = ae[o][i][3] + bv; v1.w = ao[o][i][3] + bv;
            if (RELU) {
                v0.x = fmaxf(v0.x, 0.f); v0.y = fmaxf(v0.y, 0.f);
                v0.z = fmaxf(v0.z, 0.f); v0.w = fmaxf(v0.w, 0.f);
                v1.x = fmaxf(v1.x, 0.f); v1.y = fmaxf(v1.y, 0.f);
                v1.z = fmaxf(v1.z, 0.f); v1.w = fmaxf(v1.w, 0.f);
            }
            *reinterpret_cast<float4*>(base) = v0;
            *reinterpret_cast<float4*>(base + 4) = v1;
        }
}

// ---------------- VQ: argmax(z.c - 0.5||c||^2), q = codebook[idx] ----------------
__global__ void __launch_bounds__(512)
vq_kernel(const float* __restrict__ z, const float* __restrict__ cbT,
          const float* __restrict__ cnh, const float* __restrict__ cb,
          float* __restrict__ q) {
    __shared__ __align__(16) unsigned long long red[4096];  // 32KB, aliased as cbs
    float* cbs = reinterpret_cast<float*>(red);
    __shared__ __align__(16) float zs[16 * 68];

    const int t0 = blockIdx.x * 64;
    const int b = blockIdx.y;
    const int tid = threadIdx.x;
    const int c_sub = tid & 63, t_sub = tid >> 6;
    const int cq0 = c_sub * 4, tq0 = t_sub * 4;

    float acc[2][2][4][4];
#pragma unroll
    for (int a = 0; a < 2; a++)
#pragma unroll
        for (int qq = 0; qq < 2; qq++)
#pragma unroll
            for (int i = 0; i < 4; i++)
#pragma unroll
                for (int j = 0; j < 4; j++) acc[a][qq][i][j] = 0.f;

    for (int k0 = 0; k0 < 64; k0 += 16) {
        for (int i = tid * 4; i < 8192; i += 2048) {
            int row = i >> 9, col = i & 511;
            *reinterpret_cast<float4*>(&cbs[i]) = ldf4s(&cbT[(k0 + row) * 512 + col]);
        }
        if (tid < 256) {
            int i = tid * 4;
            int row = i >> 6, col = i & 63;
            *reinterpret_cast<float4*>(&zs[row * 68 + col]) =
                ldf4s(&z[((size_t)b * 64 + k0 + row) * 2048 + t0 + col]);
        }
        __syncthreads();
#pragma unroll 2
        for (int kl = 0; kl < 16; kl++) {
            float4 cv0 = ldf4s(&cbs[kl * 512 + cq0]);
            float4 cv1 = ldf4s(&cbs[kl * 512 + cq0 + 256]);
            float4 zv0 = ldf4s(&zs[kl * 68 + tq0]);
            float4 zv1 = ldf4s(&zs[kl * 68 + tq0 + 32]);
            rank1(acc[0][0], cv0, zv0); rank1(acc[0][1], cv0, zv1);
            rank1(acc[1][0], cv1, zv0); rank1(acc[1][1], cv1, zv1);
        }
        __syncthreads();
    }
    unsigned long long bk[8];
#pragma unroll
    for (int i = 0; i < 8; i++) bk[i] = 0ULL;
#pragma unroll
    for (int cs = 0; cs < 2; cs++)
#pragma unroll
        for (int i = 0; i < 4; i++) {
            int code = cq0 + cs * 256 + i;
            float adj = __ldg(&cnh[code]);
#pragma unroll
            for (int ts = 0; ts < 2; ts++)
#pragma unroll
                for (int j = 0; j < 4; j++) {
                    float s = acc[cs][ts][i][j] - adj;
                    unsigned u = __float_as_uint(s);
                    u = (u & 0x80000000u) ? ~u : (u | 0x80000000u);
                    unsigned long long key =
                        ((unsigned long long)u << 32) | (unsigned)(511 - code);
                    int tt = ts * 4 + j;
                    if (key > bk[tt]) bk[tt] = key;
                }
        }
#pragma unroll
    for (int ts = 0; ts < 2; ts++)
#pragma unroll
        for (int j = 0; j < 4; j++) {
            int t_loc = tq0 + ts * 32 + j;
            red[t_loc * 64 + c_sub] = bk[ts * 4 + j];
        }
    __syncthreads();
    if (tid < 64) {
        unsigned long long best = 0ULL;
#pragma unroll 8
        for (int m = 0; m < 64; m++) {
            unsigned long long k = red[tid * 64 + m];
            if (k > best) best = k;
        }
        int idx = 511 - (int)(unsigned)(best & 0xffffffffULL);
        const float* crow = cb + (size_t)idx * 64;
        int t = t0 + tid;
        for (int d = 0; d < 64; d++)
            q[((size_t)b * 64 + d) * 2048 + t] = crow[d];
    }
}

// ---------------- launcher ----------------
extern "C" void kernel_launch(void* const* d_in, const int* in_sizes, int n_in,
                              void* d_out, int out_size) {
    (void)in_sizes; (void)n_in; (void)out_size;
    const float* inputs    = (const float*)d_in[0];
    const float* enc_w_in  = (const float*)d_in[1];
    const float* enc_b_in  = (const float*)d_in[2];
    const float* enc_ws    = (const float*)d_in[3];
    const float* enc_bs    = (const float*)d_in[4];
    const float* enc_w_out = (const float*)d_in[5];
    const float* enc_b_out = (const float*)d_in[6];
    const float* codebook  = (const float*)d_in[7];
    const float* dec_w_in  = (const float*)d_in[8];
    const float* dec_b_in  = (const float*)d_in[9];
    const float* dec_ws    = (const float*)d_in[10];
    const float* dec_bs    = (const float*)d_in[11];
    const float* dec_w_out = (const float*)d_in[12];
    const float* dec_b_out = (const float*)d_in[13];
    float* out = (float*)d_out;

    float *bufA, *bufB, *zb, *qb, *wt, *cbT, *cnh;
    cudaGetSymbolAddress((void**)&bufA, g_bufA);
    cudaGetSymbolAddress((void**)&bufB, g_bufB);
    cudaGetSymbolAddress((void**)&zb, g_z);
    cudaGetSymbolAddress((void**)&qb, g_q);
    cudaGetSymbolAddress((void**)&wt, g_wt);
    cudaGetSymbolAddress((void**)&cbT, g_cbT);
    cudaGetSymbolAddress((void**)&cnh, g_cnh);

    const int WSLOT = 768 * 256;  // 196608
    // repack weights
    for (int i = 0; i < 3; i++)
        repack_w_kernel<<<768, 256>>>(enc_ws + (size_t)i * 196608, wt + i * WSLOT, 256, 256);
    repack_w_kernel<<<192, 256>>>(enc_w_out, wt + 3 * WSLOT, 64, 256);
    repack_w_kernel<<<192, 256>>>(dec_w_in, wt + 4 * WSLOT, 256, 64);
    for (int i = 0; i < 3; i++)
        repack_w_kernel<<<768, 256>>>(dec_ws + (size_t)i * 196608, wt + (5 + i) * WSLOT, 256, 256);
    repack_w_kernel<<<768, 256>>>(dec_w_out, wt + 8 * WSLOT, 256, 256);
    cb_prep_kernel<<<1, 512>>>(codebook, cbT, cnh);

    // encoder
    e1_kernel<<<65536, 256>>>(inputs, enc_w_in, enc_b_in, bufA);
    conv_s2_kernel<true><<<dim3(64, 2, 16), 256>>>(bufA, wt + 0 * WSLOT, enc_bs + 0, bufB, 16384, 8192);
    conv_s2_kernel<true><<<dim3(32, 2, 16), 256>>>(bufB, wt + 1 * WSLOT, enc_bs + 256, bufA, 8192, 4096);
    conv_s2_kernel<true><<<dim3(16, 2, 16), 256>>>(bufA, wt + 2 * WSLOT, enc_bs + 512, bufB, 4096, 2048);
    conv_s1_kernel<64, false><<<dim3(16, 1, 16), 128>>>(bufB, wt + 3 * WSLOT, enc_b_out, zb, 2048, 256, 64);

    // VQ
    vq_kernel<<<dim3(32, 16), 512>>>(zb, cbT, cnh, codebook, qb);

    // decoder
    conv_s1_kernel<128, true><<<dim3(16, 2, 16), 256>>>(qb, wt + 4 * WSLOT, dec_b_in, bufA, 2048, 64, 256);
    convT_kernel<true><<<dim3(32, 2, 16), 256>>>(bufA, wt + 5 * WSLOT, dec_bs + 0, bufB, 2048, 4096);
    convT_kernel<true><<<dim3(64, 2, 16), 256>>>(bufB, wt + 6 * WSLOT, dec_bs + 256, bufA, 4096, 8192);
    convT_kernel<true><<<dim3(128, 2, 16), 256>>>(bufA, wt + 7 * WSLOT, dec_bs + 512, bufB, 8192, 16384);
    convT_kernel<false><<<dim3(256, 2, 16), 256>>>(bufB, wt + 8 * WSLOT, dec_b_out, out, 16384, 32768);
}

// round 2
// speedup vs baseline: 1.0481x; 1.0481x over previous
#include <cuda_runtime.h>

#define DI __device__ __forceinline__
typedef unsigned long long u64;

// ---------------- static scratch (no allocs allowed) ----------------
__device__ float g_bufA[67108864];          // 256 MiB: up to [16,256,16384]
__device__ float g_bufB[67108864];          // 256 MiB
__device__ float g_z[16 * 64 * 2048];       // encoder latent
__device__ float g_q[16 * 64 * 2048];       // quantized latent
__device__ float g_wt[9 * 768 * 256];       // repacked weights, 9 slots
__device__ float g_cbT[64 * 512];           // codebook transposed [k][code]
__device__ float g_cnh[512];                // 0.5*||c||^2

DI float4 ldf4s(const float* p) { return *reinterpret_cast<const float4*>(p); }

// ---- packed f32x2 helpers (FFMA2: the 2x fp32 path ptxas never emits) ----
DI u64 pk2(float x, float y) {
    u64 r; asm("mov.b64 %0, {%1, %2};" : "=l"(r) : "f"(x), "f"(y)); return r;
}
DI u64 dup2(float x) { return pk2(x, x); }
DI void upk2(u64 v, float& x, float& y) {
    asm("mov.b64 {%0, %1}, %2;" : "=f"(x), "=f"(y) : "l"(v));
}
DI u64 fma2(u64 a, u64 b, u64 c) {
    u64 d; asm("fma.rn.f32x2 %0, %1, %2, %3;" : "=l"(d) : "l"(a), "l"(b), "l"(c));
    return d;
}
DI void wsplit(float4 w, u64 w2[2]) { w2[0] = pk2(w.x, w.y); w2[1] = pk2(w.z, w.w); }
DI void dup4(float4 v, u64 d[4]) {
    d[0] = dup2(v.x); d[1] = dup2(v.y); d[2] = dup2(v.z); d[3] = dup2(v.w);
}
// acc[p][j] += w2[p] (oc pair) * xd[j] (t dup)
DI void rank1p(u64 acc[2][4], const u64 w2[2], const u64 xd[4]) {
#pragma unroll
    for (int p = 0; p < 2; p++)
#pragma unroll
        for (int j = 0; j < 4; j++) acc[p][j] = fma2(w2[p], xd[j], acc[p][j]);
}

// ---------------- weight repack: w[oc][ic][k] -> wt[(ic*3+k)][oc] ----------------
__global__ void repack_w_kernel(const float* __restrict__ w, float* __restrict__ wt,
                                int OC, int IC) {
    int i = blockIdx.x * 256 + threadIdx.x;
    int n = OC * IC * 3;
    if (i < n) {
        int oc = i / (IC * 3);
        int r = i - oc * IC * 3;
        wt[r * OC + oc] = w[i];
    }
}

// ---------------- codebook prep ----------------
__global__ void cb_prep_kernel(const float* __restrict__ cb, float* __restrict__ cbT,
                               float* __restrict__ cnh) {
    int c = threadIdx.x;  // 512 threads
    float s = 0.f;
    for (int k = 0; k < 64; k++) {
        float v = cb[c * 64 + k];
        cbT[k * 512 + c] = v;
        s += v * v;
    }
    cnh[c] = 0.5f * s;
}

// ---------------- encoder layer 1: in_ch=1, stride 2, relu ----------------
__global__ void e1_kernel(const float* __restrict__ x, const float* __restrict__ w,
                          const float* __restrict__ bias, float* __restrict__ out) {
    int idx = blockIdx.x * blockDim.x + threadIdx.x;  // 16*256*4096 total
    int t4 = idx & 4095;
    int oc = (idx >> 12) & 255;
    int b = idx >> 20;
    int t = t4 * 4;
    const float* xr = x + (size_t)b * 32768;
    float w0 = w[oc * 3], w1 = w[oc * 3 + 1], w2 = w[oc * 3 + 2], bv = bias[oc];
    float v[4];
#pragma unroll
    for (int j = 0; j < 4; j++) {
        int p = 2 * (t + j);
        float xm = (p - 1 >= 0) ? xr[p - 1] : 0.f;
        float r = bv + w0 * xm + w1 * xr[p] + w2 * xr[p + 1];
        v[j] = fmaxf(r, 0.f);
    }
    float4 o4 = make_float4(v[0], v[1], v[2], v[3]);
    *reinterpret_cast<float4*>(out + (size_t)(b * 256 + oc) * 16384 + t) = o4;
}

// ---------------- stride-2 conv, IC=OC=256 ----------------
template <bool RELU>
__global__ void __launch_bounds__(256)
conv_s2_kernel(const float* __restrict__ x, const float* __restrict__ wt,
               const float* __restrict__ bias, float* __restrict__ out,
               int Tin, int Tout) {
    __shared__ __align__(16) float ws[48 * 128];
    __shared__ __align__(16) float xE[16 * 128];
    __shared__ __align__(16) float xO[16 * 132];

    const int t0 = blockIdx.x * 128;
    const int oc0 = blockIdx.y * 128;
    const int b = blockIdx.z;
    const int tid = threadIdx.x;
    const float* xb = x + (size_t)b * 256 * Tin;

    const int oc_sub = tid & 15, t_sub = tid >> 4;
    const int ocq0 = oc_sub * 4, tq0 = t_sub * 4;

    u64 acc2[2][2][2][4];  // [oc half][t half][oc pair][t]
#pragma unroll
    for (int a = 0; a < 2; a++)
#pragma unroll
        for (int q = 0; q < 2; q++)
#pragma unroll
            for (int p = 0; p < 2; p++)
#pragma unroll
                for (int j = 0; j < 4; j++) acc2[a][q][p][j] = 0ULL;

    for (int ic0 = 0; ic0 < 256; ic0 += 16) {
        for (int i = tid * 4; i < 48 * 128; i += 256 * 4) {
            int row = i >> 7, col = i & 127;
            *reinterpret_cast<float4*>(&ws[i]) =
                ldf4s(&wt[(size_t)(ic0 * 3 + row) * 256 + oc0 + col]);
        }
        for (int i = tid; i < 16 * 257; i += 256) {
            int icl = i / 257, r = i - icl * 257;
            int gp = 2 * t0 - 1 + r;
            float v = (gp >= 0) ? xb[(size_t)(ic0 + icl) * Tin + gp] : 0.f;
            if (r & 1) xE[icl * 128 + ((r - 1) >> 1)] = v;   // even global pos
            else       xO[icl * 132 + (r >> 1)] = v;         // odd global pos
        }
        __syncthreads();
#pragma unroll 2
        for (int icl = 0; icl < 16; icl++) {
            const float* wr = &ws[icl * 3 * 128];
            u64 w00p[2], w10p[2], w01p[2], w11p[2], w02p[2], w12p[2];
            wsplit(ldf4s(wr + ocq0), w00p);        wsplit(ldf4s(wr + ocq0 + 64), w10p);
            wsplit(ldf4s(wr + 128 + ocq0), w01p);  wsplit(ldf4s(wr + 128 + ocq0 + 64), w11p);
            wsplit(ldf4s(wr + 256 + ocq0), w02p);  wsplit(ldf4s(wr + 256 + ocq0 + 64), w12p);
            const float* xe = &xE[icl * 128];
            const float* xo = &xO[icl * 132];
            float4 xe0 = ldf4s(xe + tq0), xe1 = ldf4s(xe + tq0 + 64);
            float4 xo0 = ldf4s(xo + tq0), xo1 = ldf4s(xo + tq0 + 64);
            float xo0h = xo[tq0 + 4], xo1h = xo[tq0 + 68];
            u64 xo0d[4], xo1d[4], xe0d[4], xe1d[4];
            dup4(xo0, xo0d); dup4(xo1, xo1d); dup4(xe0, xe0d); dup4(xe1, xe1d);
            u64 xs0d[4] = {xo0d[1], xo0d[2], xo0d[3], dup2(xo0h)};
            u64 xs1d[4] = {xo1d[1], xo1d[2], xo1d[3], dup2(xo1h)};
            rank1p(acc2[0][0], w00p, xo0d); rank1p(acc2[0][1], w00p, xo1d);   // k=0
            rank1p(acc2[1][0], w10p, xo0d); rank1p(acc2[1][1], w10p, xo1d);
            rank1p(acc2[0][0], w01p, xe0d); rank1p(acc2[0][1], w01p, xe1d);   // k=1
            rank1p(acc2[1][0], w11p, xe0d); rank1p(acc2[1][1], w11p, xe1d);
            rank1p(acc2[0][0], w02p, xs0d); rank1p(acc2[0][1], w02p, xs1d);   // k=2
            rank1p(acc2[1][0], w12p, xs0d); rank1p(acc2[1][1], w12p, xs1d);
        }
        __syncthreads();
    }
#pragma unroll
    for (int o = 0; o < 2; o++) {
        float af[4][2][4];
#pragma unroll
        for (int q = 0; q < 2; q++)
#pragma unroll
            for (int p = 0; p < 2; p++)
#pragma unroll
                for (int j = 0; j < 4; j++)
                    upk2(acc2[o][q][p][j], af[2 * p][q][j], af[2 * p + 1][q][j]);
#pragma unroll
        for (int i = 0; i < 4; i++) {
            int oc = oc0 + ocq0 + o * 64 + i;
            float bv = bias[oc];
            float* orow = out + (size_t)(b * 256 + oc) * Tout + t0;
#pragma unroll
            for (int q = 0; q < 2; q++) {
                float4 v;
                v.x = af[i][q][0] + bv; v.y = af[i][q][1] + bv;
                v.z = af[i][q][2] + bv; v.w = af[i][q][3] + bv;
                if (RELU) {
                    v.x = fmaxf(v.x, 0.f); v.y = fmaxf(v.y, 0.f);
                    v.z = fmaxf(v.z, 0.f); v.w = fmaxf(v.w, 0.f);
                }
                *reinterpret_cast<float4*>(orow + q * 64 + tq0) = v;
            }
        }
    }
}

// ---------------- stride-1 conv, generic IC/OC ----------------
template <int BO, bool RELU>
__global__ void conv_s1_kernel(const float* __restrict__ x, const float* __restrict__ wt,
                               const float* __restrict__ bias, float* __restrict__ out,
                               int T, int IC, int OC) {
    const int THREADS = BO * 2;
    __shared__ __align__(16) float ws[48 * BO];
    __shared__ __align__(16) float xs[16 * 132];
    const int t0 = blockIdx.x * 128;
    const int oc0 = blockIdx.y * BO;
    const int b = blockIdx.z;
    const int tid = threadIdx.x;
    const int OCS = BO / 8;
    const int oc_sub = tid % OCS, t_sub = tid / OCS;
    const int ocq0 = oc_sub * 4, tq0 = t_sub * 4;
    const float* xb = x + (size_t)b * IC * T;

    u64 acc2[2][2][2][4];
#pragma unroll
    for (int a = 0; a < 2; a++)
#pragma unroll
        for (int q = 0; q < 2; q++)
#pragma unroll
            for (int p = 0; p < 2; p++)
#pragma unroll
                for (int j = 0; j < 4; j++) acc2[a][q][p][j] = 0ULL;

    for (int ic0 = 0; ic0 < IC; ic0 += 16) {
        for (int i = tid * 4; i < 48 * BO; i += THREADS * 4) {
            int row = i / BO, col = i % BO;
            *reinterpret_cast<float4*>(&ws[i]) =
                ldf4s(&wt[(size_t)(ic0 * 3 + row) * OC + oc0 + col]);
        }
        for (int i = tid; i < 16 * 130; i += THREADS) {
            int icl = i / 130, r = i - icl * 130;
            int gp = t0 - 1 + r;
            float v = (gp >= 0 && gp < T) ? xb[(size_t)(ic0 + icl) * T + gp] : 0.f;
            xs[icl * 132 + r] = v;
        }
        __syncthreads();
#pragma unroll 2
        for (int icl = 0; icl < 16; icl++) {
            const float* wr = &ws[icl * 3 * BO];
            u64 w00p[2], w10p[2], w01p[2], w11p[2], w02p[2], w12p[2];
            wsplit(ldf4s(wr + ocq0), w00p);          wsplit(ldf4s(wr + ocq0 + BO / 2), w10p);
            wsplit(ldf4s(wr + BO + ocq0), w01p);     wsplit(ldf4s(wr + BO + ocq0 + BO / 2), w11p);
            wsplit(ldf4s(wr + 2 * BO + ocq0), w02p); wsplit(ldf4s(wr + 2 * BO + ocq0 + BO / 2), w12p);
            const float* xr = &xs[icl * 132];
            float4 a0 = ldf4s(xr + tq0);
            float h0a = xr[tq0 + 4], h0b = xr[tq0 + 5];
            float4 a1 = ldf4s(xr + tq0 + 64);
            float h1a = xr[tq0 + 68], h1b = xr[tq0 + 69];
            u64 a0d[4], a1d[4];
            dup4(a0, a0d); dup4(a1, a1d);
            u64 h0ad = dup2(h0a), h0bd = dup2(h0b);
            u64 h1ad = dup2(h1a), h1bd = dup2(h1b);
            u64 x00d[4] = {a0d[0], a0d[1], a0d[2], a0d[3]};
            u64 x01d[4] = {a0d[1], a0d[2], a0d[3], h0ad};
            u64 x02d[4] = {a0d[2], a0d[3], h0ad, h0bd};
            u64 x10d[4] = {a1d[0], a1d[1], a1d[2], a1d[3]};
            u64 x11d[4] = {a1d[1], a1d[2], a1d[3], h1ad};
            u64 x12d[4] = {a1d[2], a1d[3], h1ad, h1bd};
            rank1p(acc2[0][0], w00p, x00d); rank1p(acc2[0][1], w00p, x10d);
            rank1p(acc2[1][0], w10p, x00d); rank1p(acc2[1][1], w10p, x10d);
            rank1p(acc2[0][0], w01p, x01d); rank1p(acc2[0][1], w01p, x11d);
            rank1p(acc2[1][0], w11p, x01d); rank1p(acc2[1][1], w11p, x11d);
            rank1p(acc2[0][0], w02p, x02d); rank1p(acc2[0][1], w02p, x12d);
            rank1p(acc2[1][0], w12p, x02d); rank1p(acc2[1][1], w12p, x12d);
        }
        __syncthreads();
    }
#pragma unroll
    for (int o = 0; o < 2; o++) {
        float af[4][2][4];
#pragma unroll
        for (int q = 0; q < 2; q++)
#pragma unroll
            for (int p = 0; p < 2; p++)
#pragma unroll
                for (int j = 0; j < 4; j++)
                    upk2(acc2[o][q][p][j], af[2 * p][q][j], af[2 * p + 1][q][j]);
#pragma unroll
        for (int i = 0; i < 4; i++) {
            int oc = oc0 + ocq0 + o * (BO / 2) + i;
            float bv = bias[oc];
            float* orow = out + (size_t)(b * OC + oc) * T + t0;
#pragma unroll
            for (int q = 0; q < 2; q++) {
                float4 v;
                v.x = af[i][q][0] + bv; v.y = af[i][q][1] + bv;
                v.z = af[i][q][2] + bv; v.w = af[i][q][3] + bv;
                if (RELU) {
                    v.x = fmaxf(v.x, 0.f); v.y = fmaxf(v.y, 0.f);
                    v.z = fmaxf(v.z, 0.f); v.w = fmaxf(v.w, 0.f);
                }
                *reinterpret_cast<float4*>(orow + q * 64 + tq0) = v;
            }
        }
    }
}

// ---------------- transposed conv (stride 2 upsample), IC=OC=256 ----------------
// out[2m]   = sum_i x[i][m]   * w[o][i][1]
// out[2m+1] = sum_i x[i][m] * w[o][i][0] + x[i][m+1] * w[o][i][2]
template <bool RELU>
__global__ void __launch_bounds__(256)
convT_kernel(const float* __restrict__ x, const float* __restrict__ wt,
             const float* __restrict__ bias, float* __restrict__ out,
             int Tin, int Tout) {
    __shared__ __align__(16) float ws[48 * 128];
    __shared__ __align__(16) float xs[16 * 68];

    const int m0 = blockIdx.x * 64;
    const int oc0 = blockIdx.y * 128;
    const int b = blockIdx.z;
    const int tid = threadIdx.x;
    const float* xb = x + (size_t)b * 256 * Tin;

    const int oc_sub = tid & 15, m_sub = tid >> 4;
    const int ocq0 = oc_sub * 4, mq = m_sub * 4;

    u64 ae2[2][2][4], ao2[2][2][4];  // [oc half][oc pair][m]
#pragma unroll
    for (int o = 0; o < 2; o++)
#pragma unroll
        for (int p = 0; p < 2; p++)
#pragma unroll
            for (int j = 0; j < 4; j++) { ae2[o][p][j] = 0ULL; ao2[o][p][j] = 0ULL; }

    for (int ic0 = 0; ic0 < 256; ic0 += 16) {
        for (int i = tid * 4; i < 48 * 128; i += 256 * 4) {
            int row = i >> 7, col = i & 127;
            *reinterpret_cast<float4*>(&ws[i]) =
                ldf4s(&wt[(size_t)(ic0 * 3 + row) * 256 + oc0 + col]);
        }
        for (int i = tid; i < 16 * 65; i += 256) {
            int icl = i / 65, r = i - icl * 65;
            int gp = m0 + r;
            float v = (gp < Tin) ? xb[(size_t)(ic0 + icl) * Tin + gp] : 0.f;
            xs[icl * 68 + r] = v;
        }
        __syncthreads();
#pragma unroll 2
        for (int icl = 0; icl < 16; icl++) {
            const float* wr = &ws[icl * 3 * 128];
            u64 w00p[2], w10p[2], w01p[2], w11p[2], w02p[2], w12p[2];
            wsplit(ldf4s(wr + ocq0), w00p);        wsplit(ldf4s(wr + ocq0 + 64), w10p);
            wsplit(ldf4s(wr + 128 + ocq0), w01p);  wsplit(ldf4s(wr + 128 + ocq0 + 64), w11p);
            wsplit(ldf4s(wr + 256 + ocq0), w02p);  wsplit(ldf4s(wr + 256 + ocq0 + 64), w12p);
            float4 xv = ldf4s(&xs[icl * 68 + mq]);
            float xh = xs[icl * 68 + mq + 4];
            u64 xvd[4];
            dup4(xv, xvd);
            u64 xshd[4] = {xvd[1], xvd[2], xvd[3], dup2(xh)};
            rank1p(ae2[0], w01p, xvd);  rank1p(ae2[1], w11p, xvd);    // even: k=1
            rank1p(ao2[0], w00p, xvd);  rank1p(ao2[1], w10p, xvd);    // odd:  k=0
            rank1p(ao2[0], w02p, xshd); rank1p(ao2[1], w12p, xshd);   // odd:  k=2
        }
        __syncthreads();
    }
#pragma unroll
    for (int o = 0; o < 2; o++) {
        float ef[4][4], of_[4][4];
#pragma unroll
        for (int p = 0; p < 2; p++)
#pragma unroll
            for (int j = 0; j < 4; j++) {
                upk2(ae2[o][p][j], ef[2 * p][j], ef[2 * p + 1][j]);
                upk2(ao2[o][p][j], of_[2 * p][j], of_[2 * p + 1][j]);
            }
#pragma unroll
        for (int i = 0; i < 4; i++) {
            int oc = oc0 + ocq0 + o * 64 + i;
            float bv = bias[oc];
            float* base = out + (size_t)(b * 256 + oc) * Tout + 2 * (m0 + mq);
            float4 v0, v1;
            v0.x = ef[i][0] + bv; v0.y = of_[i][0] + bv;
            v0.z = ef[i][1] + bv; v0.w = of_[i][1] + bv;
            v1.x = ef[i][2] + bv; v1.y = of_[i][2] + bv;
            v1.z = ef[i][3] + bv; v1.w = of_[i][3] + bv;
            if (RELU) {
                v0.x = fmaxf(v0.x, 0.f); v0.y = fmaxf(v0.y, 0.f);
                v0.z = fmaxf(v0.z, 0.f); v0.w = fmaxf(v0.w, 0.f);
                v1.x = fmaxf(v1.x, 0.f); v1.y = fmaxf(v1.y, 0.f);
                v1.z = fmaxf(v1.z, 0.f); v1.w = fmaxf(v1.w, 0.f);
            }
            *reinterpret_cast<float4*>(base) = v0;
            *reinterpret_cast<float4*>(base + 4) = v1;
        }
    }
}

// ---------------- VQ: argmax(z.c - 0.5||c||^2), q = codebook[idx] ----------------
__global__ void __launch_bounds__(512)
vq_kernel(const float* __restrict__ z, const float* __restrict__ cbT,
          const float* __restrict__ cnh, const float* __restrict__ cb,
          float* __restrict__ q) {
    __shared__ __align__(16) unsigned long long red[4096];  // 32KB, aliased as cbs
    float* cbs = reinterpret_cast<float*>(red);
    __shared__ __align__(16) float zs[16 * 68];

    const int t0 = blockIdx.x * 64;
    const int b = blockIdx.y;
    const int tid = threadIdx.x;
    const int c_sub = tid & 63, t_sub = tid >> 6;
    const int cq0 = c_sub * 4, tq0 = t_sub * 4;

    u64 acc2[2][2][2][4];  // [code half][t half][code pair][t]
#pragma unroll
    for (int a = 0; a < 2; a++)
#pragma unroll
        for (int qq = 0; qq < 2; qq++)
#pragma unroll
            for (int p = 0; p < 2; p++)
#pragma unroll
                for (int j = 0; j < 4; j++) acc2[a][qq][p][j] = 0ULL;

    for (int k0 = 0; k0 < 64; k0 += 16) {
        for (int i = tid * 4; i < 8192; i += 2048) {
            int row = i >> 9, col = i & 511;
            *reinterpret_cast<float4*>(&cbs[i]) = ldf4s(&cbT[(k0 + row) * 512 + col]);
        }
        if (tid < 256) {
            int i = tid * 4;
            int row = i >> 6, col = i & 63;
            *reinterpret_cast<float4*>(&zs[row * 68 + col]) =
                ldf4s(&z[((size_t)b * 64 + k0 + row) * 2048 + t0 + col]);
        }
        __syncthreads();
#pragma unroll 2
        for (int kl = 0; kl < 16; kl++) {
            u64 cv0p[2], cv1p[2];
            wsplit(ldf4s(&cbs[kl * 512 + cq0]), cv0p);
            wsplit(ldf4s(&cbs[kl * 512 + cq0 + 256]), cv1p);
            float4 zv0 = ldf4s(&zs[kl * 68 + tq0]);
            float4 zv1 = ldf4s(&zs[kl * 68 + tq0 + 32]);
            u64 zv0d[4], zv1d[4];
            dup4(zv0, zv0d); dup4(zv1, zv1d);
            rank1p(acc2[0][0], cv0p, zv0d); rank1p(acc2[0][1], cv0p, zv1d);
            rank1p(acc2[1][0], cv1p, zv0d); rank1p(acc2[1][1], cv1p, zv1d);
        }
        __syncthreads();
    }
    unsigned long long bk[8];
#pragma unroll
    for (int i = 0; i < 8; i++) bk[i] = 0ULL;
#pragma unroll
    for (int cs = 0; cs < 2; cs++)
#pragma unroll
        for (int p = 0; p < 2; p++) {
            int c0 = cq0 + cs * 256 + 2 * p;
            float adj0 = __ldg(&cnh[c0]);
            float adj1 = __ldg(&cnh[c0 + 1]);
#pragma unroll
            for (int ts = 0; ts < 2; ts++)
#pragma unroll
                for (int j = 0; j < 4; j++) {
                    float s0, s1;
                    upk2(acc2[cs][ts][p][j], s0, s1);
                    s0 -= adj0; s1 -= adj1;
                    int tt = ts * 4 + j;
                    unsigned u0 = __float_as_uint(s0);
                    u0 = (u0 & 0x80000000u) ? ~u0 : (u0 | 0x80000000u);
                    unsigned long long key0 =
                        ((unsigned long long)u0 << 32) | (unsigned)(511 - c0);
                    if (key0 > bk[tt]) bk[tt] = key0;
                    unsigned u1 = __float_as_uint(s1);
                    u1 = (u1 & 0x80000000u) ? ~u1 : (u1 | 0x80000000u);
                    unsigned long long key1 =
                        ((unsigned long long)u1 << 32) | (unsigned)(511 - (c0 + 1));
                    if (key1 > bk[tt]) bk[tt] = key1;
                }
        }
#pragma unroll
    for (int ts = 0; ts < 2; ts++)
#pragma unroll
        for (int j = 0; j < 4; j++) {
            int t_loc = tq0 + ts * 32 + j;
            red[t_loc * 64 + c_sub] = bk[ts * 4 + j];
        }
    __syncthreads();
    if (tid < 64) {
        unsigned long long best = 0ULL;
#pragma unroll 8
        for (int m = 0; m < 64; m++) {
            unsigned long long k = red[tid * 64 + m];
            if (k > best) best = k;
        }
        int idx = 511 - (int)(unsigned)(best & 0xffffffffULL);
        const float* crow = cb + (size_t)idx * 64;
        int t = t0 + tid;
        for (int d = 0; d < 64; d++)
            q[((size_t)b * 64 + d) * 2048 + t] = crow[d];
    }
}

// ---------------- launcher ----------------
extern "C" void kernel_launch(void* const* d_in, const int* in_sizes, int n_in,
                              void* d_out, int out_size) {
    (void)in_sizes; (void)n_in; (void)out_size;
    const float* inputs    = (const float*)d_in[0];
    const float* enc_w_in  = (const float*)d_in[1];
    const float* enc_b_in  = (const float*)d_in[2];
    const float* enc_ws    = (const float*)d_in[3];
    const float* enc_bs    = (const float*)d_in[4];
    const float* enc_w_out = (const float*)d_in[5];
    const float* enc_b_out = (const float*)d_in[6];
    const float* codebook  = (const float*)d_in[7];
    const float* dec_w_in  = (const float*)d_in[8];
    const float* dec_b_in  = (const float*)d_in[9];
    const float* dec_ws    = (const float*)d_in[10];
    const float* dec_bs    = (const float*)d_in[11];
    const float* dec_w_out = (const float*)d_in[12];
    const float* dec_b_out = (const float*)d_in[13];
    float* out = (float*)d_out;

    float *bufA, *bufB, *zb, *qb, *wt, *cbT, *cnh;
    cudaGetSymbolAddress((void**)&bufA, g_bufA);
    cudaGetSymbolAddress((void**)&bufB, g_bufB);
    cudaGetSymbolAddress((void**)&zb, g_z);
    cudaGetSymbolAddress((void**)&qb, g_q);
    cudaGetSymbolAddress((void**)&wt, g_wt);
    cudaGetSymbolAddress((void**)&cbT, g_cbT);
    cudaGetSymbolAddress((void**)&cnh, g_cnh);

    const int WSLOT = 768 * 256;  // 196608
    // repack weights
    for (int i = 0; i < 3; i++)
        repack_w_kernel<<<768, 256>>>(enc_ws + (size_t)i * 196608, wt + i * WSLOT, 256, 256);
    repack_w_kernel<<<192, 256>>>(enc_w_out, wt + 3 * WSLOT, 64, 256);
    repack_w_kernel<<<192, 256>>>(dec_w_in, wt + 4 * WSLOT, 256, 64);
    for (int i = 0; i < 3; i++)
        repack_w_kernel<<<768, 256>>>(dec_ws + (size_t)i * 196608, wt + (5 + i) * WSLOT, 256, 256);
    repack_w_kernel<<<768, 256>>>(dec_w_out, wt + 8 * WSLOT, 256, 256);
    cb_prep_kernel<<<1, 512>>>(codebook, cbT, cnh);

    // encoder
    e1_kernel<<<65536, 256>>>(inputs, enc_w_in, enc_b_in, bufA);
    conv_s2_kernel<true><<<dim3(64, 2, 16), 256>>>(bufA, wt + 0 * WSLOT, enc_bs + 0, bufB, 16384, 8192);
    conv_s2_kernel<true><<<dim3(32, 2, 16), 256>>>(bufB, wt + 1 * WSLOT, enc_bs + 256, bufA, 8192, 4096);
    conv_s2_kernel<true><<<dim3(16, 2, 16), 256>>>(bufA, wt + 2 * WSLOT, enc_bs + 512, bufB, 4096, 2048);
    conv_s1_kernel<64, false><<<dim3(16, 1, 16), 128>>>(bufB, wt + 3 * WSLOT, enc_b_out, zb, 2048, 256, 64);

    // VQ
    vq_kernel<<<dim3(32, 16), 512>>>(zb, cbT, cnh, codebook, qb);

    // decoder
    conv_s1_kernel<128, true><<<dim3(16, 2, 16), 256>>>(qb, wt + 4 * WSLOT, dec_b_in, bufA, 2048, 64, 256);
    convT_kernel<true><<<dim3(32, 2, 16), 256>>>(bufA, wt + 5 * WSLOT, dec_bs + 0, bufB, 2048, 4096);
    convT_kernel<true><<<dim3(64, 2, 16), 256>>>(bufB, wt + 6 * WSLOT, dec_bs + 256, bufA, 4096, 8192);
    convT_kernel<true><<<dim3(128, 2, 16), 256>>>(bufA, wt + 7 * WSLOT, dec_bs + 512, bufB, 8192, 16384);
    convT_kernel<false><<<dim3(256, 2, 16), 256>>>(bufB, wt + 8 * WSLOT, dec_b_out, out, 16384, 32768);
}

// round 3
// speedup vs baseline: 1.0481x; 1.0001x over previous
#include <cuda_runtime.h>

#define DI __device__ __forceinline__
typedef unsigned long long u64;

// ---------------- static scratch (no allocs allowed) ----------------
__device__ float g_bufA[67108864];          // 256 MiB: up to [16,256,16384]
__device__ float g_bufB[67108864];          // 256 MiB
__device__ float g_z[16 * 64 * 2048];       // encoder latent
__device__ float g_q[16 * 64 * 2048];       // quantized latent
__device__ float g_wt[9 * 768 * 256];       // repacked weights, 9 slots
__device__ float g_cbT[64 * 512];           // codebook transposed [k][code]
__device__ float g_cnh[512];                // 0.5*||c||^2

DI float4 ldf4s(const float* p) { return *reinterpret_cast<const float4*>(p); }

// ---- packed f32x2 helpers (FFMA2: the 2x fp32 path ptxas never emits) ----
DI u64 pk2(float x, float y) {
    u64 r; asm("mov.b64 %0, {%1, %2};" : "=l"(r) : "f"(x), "f"(y)); return r;
}
DI u64 dup2(float x) { return pk2(x, x); }
DI void upk2(u64 v, float& x, float& y) {
    asm("mov.b64 {%0, %1}, %2;" : "=f"(x), "=f"(y) : "l"(v));
}
DI u64 fma2(u64 a, u64 b, u64 c) {
    u64 d; asm("fma.rn.f32x2 %0, %1, %2, %3;" : "=l"(d) : "l"(a), "l"(b), "l"(c));
    return d;
}
DI void wsplit(float4 w, u64 w2[2]) { w2[0] = pk2(w.x, w.y); w2[1] = pk2(w.z, w.w); }
DI void dup4(float4 v, u64 d[4]) {
    d[0] = dup2(v.x); d[1] = dup2(v.y); d[2] = dup2(v.z); d[3] = dup2(v.w);
}
// acc[p][j] += w2[p] (oc pair) * xd[j] (t dup)
DI void rank1p(u64 acc[2][4], const u64 w2[2], const u64 xd[4]) {
#pragma unroll
    for (int p = 0; p < 2; p++)
#pragma unroll
        for (int j = 0; j < 4; j++) acc[p][j] = fma2(w2[p], xd[j], acc[p][j]);
}

// ---------------- weight repack: w[oc][ic][k] -> wt[(ic*3+k)][oc] ----------------
__global__ void repack_w_kernel(const float* __restrict__ w, float* __restrict__ wt,
                                int OC, int IC) {
    int i = blockIdx.x * 256 + threadIdx.x;
    int n = OC * IC * 3;
    if (i < n) {
        int oc = i / (IC * 3);
        int r = i - oc * IC * 3;
        wt[r * OC + oc] = w[i];
    }
}

// ---------------- codebook prep ----------------
__global__ void cb_prep_kernel(const float* __restrict__ cb, float* __restrict__ cbT,
                               float* __restrict__ cnh) {
    int c = threadIdx.x;  // 512 threads
    float s = 0.f;
    for (int k = 0; k < 64; k++) {
        float v = cb[c * 64 + k];
        cbT[k * 512 + c] = v;
        s += v * v;
    }
    cnh[c] = 0.5f * s;
}

// ---------------- encoder layer 1: in_ch=1, stride 2, relu ----------------
__global__ void e1_kernel(const float* __restrict__ x, const float* __restrict__ w,
                          const float* __restrict__ bias, float* __restrict__ out) {
    int idx = blockIdx.x * blockDim.x + threadIdx.x;  // 16*256*4096 total
    int t4 = idx & 4095;
    int oc = (idx >> 12) & 255;
    int b = idx >> 20;
    int t = t4 * 4;
    const float* xr = x + (size_t)b * 32768;
    float w0 = w[oc * 3], w1 = w[oc * 3 + 1], w2 = w[oc * 3 + 2], bv = bias[oc];
    float v[4];
#pragma unroll
    for (int j = 0; j < 4; j++) {
        int p = 2 * (t + j);
        float xm = (p - 1 >= 0) ? xr[p - 1] : 0.f;
        float r = bv + w0 * xm + w1 * xr[p] + w2 * xr[p + 1];
        v[j] = fmaxf(r, 0.f);
    }
    float4 o4 = make_float4(v[0], v[1], v[2], v[3]);
    *reinterpret_cast<float4*>(out + (size_t)(b * 256 + oc) * 16384 + t) = o4;
}

// ---------------- stride-2 conv, IC=OC=256 ----------------
template <bool RELU>
__global__ void __launch_bounds__(256)
conv_s2_kernel(const float* __restrict__ x, const float* __restrict__ wt,
               const float* __restrict__ bias, float* __restrict__ out,
               int Tin, int Tout) {
    __shared__ __align__(16) float ws[48 * 128];
    __shared__ __align__(16) float xE[16 * 128];
    __shared__ __align__(16) float xO[16 * 132];

    const int t0 = blockIdx.x * 128;
    const int oc0 = blockIdx.y * 128;
    const int b = blockIdx.z;
    const int tid = threadIdx.x;
    const float* xb = x + (size_t)b * 256 * Tin;

    const int oc_sub = tid & 15, t_sub = tid >> 4;
    const int ocq0 = oc_sub * 4, tq0 = t_sub * 4;

    u64 acc2[2][2][2][4];  // [oc half][t half][oc pair][t]
#pragma unroll
    for (int a = 0; a < 2; a++)
#pragma unroll
        for (int q = 0; q < 2; q++)
#pragma unroll
            for (int p = 0; p < 2; p++)
#pragma unroll
                for (int j = 0; j < 4; j++) acc2[a][q][p][j] = 0ULL;

    for (int ic0 = 0; ic0 < 256; ic0 += 16) {
        for (int i = tid * 4; i < 48 * 128; i += 256 * 4) {
            int row = i >> 7, col = i & 127;
            *reinterpret_cast<float4*>(&ws[i]) =
                ldf4s(&wt[(size_t)(ic0 * 3 + row) * 256 + oc0 + col]);
        }
        for (int i = tid; i < 16 * 257; i += 256) {
            int icl = i / 257, r = i - icl * 257;
            int gp = 2 * t0 - 1 + r;
            float v = (gp >= 0) ? xb[(size_t)(ic0 + icl) * Tin + gp] : 0.f;
            if (r & 1) xE[icl * 128 + ((r - 1) >> 1)] = v;   // even global pos
            else       xO[icl * 132 + (r >> 1)] = v;         // odd global pos
        }
        __syncthreads();
#pragma unroll 2
        for (int icl = 0; icl < 16; icl++) {
            const float* wr = &ws[icl * 3 * 128];
            u64 w00p[2], w10p[2], w01p[2], w11p[2], w02p[2], w12p[2];
            wsplit(ldf4s(wr + ocq0), w00p);        wsplit(ldf4s(wr + ocq0 + 64), w10p);
            wsplit(ldf4s(wr + 128 + ocq0), w01p);  wsplit(ldf4s(wr + 128 + ocq0 + 64), w11p);
            wsplit(ldf4s(wr + 256 + ocq0), w02p);  wsplit(ldf4s(wr + 256 + ocq0 + 64), w12p);
            const float* xe = &xE[icl * 128];
            const float* xo = &xO[icl * 132];
            float4 xe0 = ldf4s(xe + tq0), xe1 = ldf4s(xe + tq0 + 64);
            float4 xo0 = ldf4s(xo + tq0), xo1 = ldf4s(xo + tq0 + 64);
            float xo0h = xo[tq0 + 4], xo1h = xo[tq0 + 68];
            u64 xo0d[4], xo1d[4], xe0d[4], xe1d[4];
            dup4(xo0, xo0d); dup4(xo1, xo1d); dup4(xe0, xe0d); dup4(xe1, xe1d);
            u64 xs0d[4] = {xo0d[1], xo0d[2], xo0d[3], dup2(xo0h)};
            u64 xs1d[4] = {xo1d[1], xo1d[2], xo1d[3], dup2(xo1h)};
            rank1p(acc2[0][0], w00p, xo0d); rank1p(acc2[0][1], w00p, xo1d);   // k=0
            rank1p(acc2[1][0], w10p, xo0d); rank1p(acc2[1][1], w10p, xo1d);
            rank1p(acc2[0][0], w01p, xe0d); rank1p(acc2[0][1], w01p, xe1d);   // k=1
            rank1p(acc2[1][0], w11p, xe0d); rank1p(acc2[1][1], w11p, xe1d);
            rank1p(acc2[0][0], w02p, xs0d); rank1p(acc2[0][1], w02p, xs1d);   // k=2
            rank1p(acc2[1][0], w12p, xs0d); rank1p(acc2[1][1], w12p, xs1d);
        }
        __syncthreads();
    }
#pragma unroll
    for (int o = 0; o < 2; o++) {
        float af[4][2][4];
#pragma unroll
        for (int q = 0; q < 2; q++)
#pragma unroll
            for (int p = 0; p < 2; p++)
#pragma unroll
                for (int j = 0; j < 4; j++)
                    upk2(acc2[o][q][p][j], af[2 * p][q][j], af[2 * p + 1][q][j]);
#pragma unroll
        for (int i = 0; i < 4; i++) {
            int oc = oc0 + ocq0 + o * 64 + i;
            float bv = bias[oc];
            float* orow = out + (size_t)(b * 256 + oc) * Tout + t0;
#pragma unroll
            for (int q = 0; q < 2; q++) {
                float4 v;
                v.x = af[i][q][0] + bv; v.y = af[i][q][1] + bv;
                v.z = af[i][q][2] + bv; v.w = af[i][q][3] + bv;
                if (RELU) {
                    v.x = fmaxf(v.x, 0.f); v.y = fmaxf(v.y, 0.f);
                    v.z = fmaxf(v.z, 0.f); v.w = fmaxf(v.w, 0.f);
                }
                *reinterpret_cast<float4*>(orow + q * 64 + tq0) = v;
            }
        }
    }
}

// ---------------- stride-1 conv, generic IC/OC ----------------
template <int BO, bool RELU>
__global__ void conv_s1_kernel(const float* __restrict__ x, const float* __restrict__ wt,
                               const float* __restrict__ bias, float* __restrict__ out,
                               int T, int IC, int OC) {
    const int THREADS = BO * 2;
    __shared__ __align__(16) float ws[48 * BO];
    __shared__ __align__(16) float xs[16 * 132];
    const int t0 = blockIdx.x * 128;
    const int oc0 = blockIdx.y * BO;
    const int b = blockIdx.z;
    const int tid = threadIdx.x;
    const int OCS = BO / 8;
    const int oc_sub = tid % OCS, t_sub = tid / OCS;
    const int ocq0 = oc_sub * 4, tq0 = t_sub * 4;
    const float* xb = x + (size_t)b * IC * T;

    u64 acc2[2][2][2][4];
#pragma unroll
    for (int a = 0; a < 2; a++)
#pragma unroll
        for (int q = 0; q < 2; q++)
#pragma unroll
            for (int p = 0; p < 2; p++)
#pragma unroll
                for (int j = 0; j < 4; j++) acc2[a][q][p][j] = 0ULL;

    for (int ic0 = 0; ic0 < IC; ic0 += 16) {
        for (int i = tid * 4; i < 48 * BO; i += THREADS * 4) {
            int row = i / BO, col = i % BO;
            *reinterpret_cast<float4*>(&ws[i]) =
                ldf4s(&wt[(size_t)(ic0 * 3 + row) * OC + oc0 + col]);
        }
        for (int i = tid; i < 16 * 130; i += THREADS) {
            int icl = i / 130, r = i - icl * 130;
            int gp = t0 - 1 + r;
            float v = (gp >= 0 && gp < T) ? xb[(size_t)(ic0 + icl) * T + gp] : 0.f;
            xs[icl * 132 + r] = v;
        }
        __syncthreads();
#pragma unroll 2
        for (int icl = 0; icl < 16; icl++) {
            const float* wr = &ws[icl * 3 * BO];
            u64 w00p[2], w10p[2], w01p[2], w11p[2], w02p[2], w12p[2];
            wsplit(ldf4s(wr + ocq0), w00p);          wsplit(ldf4s(wr + ocq0 + BO / 2), w10p);
            wsplit(ldf4s(wr + BO + ocq0), w01p);     wsplit(ldf4s(wr + BO + ocq0 + BO / 2), w11p);
            wsplit(ldf4s(wr + 2 * BO + ocq0), w02p); wsplit(ldf4s(wr + 2 * BO + ocq0 + BO / 2), w12p);
            const float* xr = &xs[icl * 132];
            float4 a0 = ldf4s(xr + tq0);
            float h0a = xr[tq0 + 4], h0b = xr[tq0 + 5];
            float4 a1 = ldf4s(xr + tq0 + 64);
            float h1a = xr[tq0 + 68], h1b = xr[tq0 + 69];
            u64 a0d[4], a1d[4];
            dup4(a0, a0d); dup4(a1, a1d);
            u64 h0ad = dup2(h0a), h0bd = dup2(h0b);
            u64 h1ad = dup2(h1a), h1bd = dup2(h1b);
            u64 x00d[4] = {a0d[0], a0d[1], a0d[2], a0d[3]};
            u64 x01d[4] = {a0d[1], a0d[2], a0d[3], h0ad};
            u64 x02d[4] = {a0d[2], a0d[3], h0ad, h0bd};
            u64 x10d[4] = {a1d[0], a1d[1], a1d[2], a1d[3]};
            u64 x11d[4] = {a1d[1], a1d[2], a1d[3], h1ad};
            u64 x12d[4] = {a1d[2], a1d[3], h1ad, h1bd};
            rank1p(acc2[0][0], w00p, x00d); rank1p(acc2[0][1], w00p, x10d);
            rank1p(acc2[1][0], w10p, x00d); rank1p(acc2[1][1], w10p, x10d);
            rank1p(acc2[0][0], w01p, x01d); rank1p(acc2[0][1], w01p, x11d);
            rank1p(acc2[1][0], w11p, x01d); rank1p(acc2[1][1], w11p, x11d);
            rank1p(acc2[0][0], w02p, x02d); rank1p(acc2[0][1], w02p, x12d);
            rank1p(acc2[1][0], w12p, x02d); rank1p(acc2[1][1], w12p, x12d);
        }
        __syncthreads();
    }
#pragma unroll
    for (int o = 0; o < 2; o++) {
        float af[4][2][4];
#pragma unroll
        for (int q = 0; q < 2; q++)
#pragma unroll
            for (int p = 0; p < 2; p++)
#pragma unroll
                for (int j = 0; j < 4; j++)
                    upk2(acc2[o][q][p][j], af[2 * p][q][j], af[2 * p + 1][q][j]);
#pragma unroll
        for (int i = 0; i < 4; i++) {
            int oc = oc0 + ocq0 + o * (BO / 2) + i;
            float bv = bias[oc];
            float* orow = out + (size_t)(b * OC + oc) * T + t0;
#pragma unroll
            for (int q = 0; q < 2; q++) {
                float4 v;
                v.x = af[i][q][0] + bv; v.y = af[i][q][1] + bv;
                v.z = af[i][q][2] + bv; v.w = af[i][q][3] + bv;
                if (RELU) {
                    v.x = fmaxf(v.x, 0.f); v.y = fmaxf(v.y, 0.f);
                    v.z = fmaxf(v.z, 0.f); v.w = fmaxf(v.w, 0.f);
                }
                *reinterpret_cast<float4*>(orow + q * 64 + tq0) = v;
            }
        }
    }
}

// ---------------- transposed conv (stride 2 upsample), IC=OC=256 ----------------
// out[2m]   = sum_i x[i][m]   * w[o][i][1]
// out[2m+1] = sum_i x[i][m] * w[o][i][0] + x[i][m+1] * w[o][i][2]
template <bool RELU>
__global__ void __launch_bounds__(256)
convT_kernel(const float* __restrict__ x, const float* __restrict__ wt,
             const float* __restrict__ bias, float* __restrict__ out,
             int Tin, int Tout) {
    __shared__ __align__(16) float ws[48 * 128];
    __shared__ __align__(16) float xs[16 * 68];

    const int m0 = blockIdx.x * 64;
    const int oc0 = blockIdx.y * 128;
    const int b = blockIdx.z;
    const int tid = threadIdx.x;
    const float* xb = x + (size_t)b * 256 * Tin;

    const int oc_sub = tid & 15, m_sub = tid >> 4;
    const int ocq0 = oc_sub * 4, mq = m_sub * 4;

    u64 ae2[2][2][4], ao2[2][2][4];  // [oc half][oc pair][m]
#pragma unroll
    for (int o = 0; o < 2; o++)
#pragma unroll
        for (int p = 0; p < 2; p++)
#pragma unroll
            for (int j = 0; j < 4; j++) { ae2[o][p][j] = 0ULL; ao2[o][p][j] = 0ULL; }

    for (int ic0 = 0; ic0 < 256; ic0 += 16) {
        for (int i = tid * 4; i < 48 * 128; i += 256 * 4) {
            int row = i >> 7, col = i & 127;
            *reinterpret_cast<float4*>(&ws[i]) =
                ldf4s(&wt[(size_t)(ic0 * 3 + row) * 256 + oc0 + col]);
        }
        for (int i = tid; i < 16 * 65; i += 256) {
            int icl = i / 65, r = i - icl * 65;
            int gp = m0 + r;
            float v = (gp < Tin) ? xb[(size_t)(ic0 + icl) * Tin + gp] : 0.f;
            xs[icl * 68 + r] = v;
        }
        __syncthreads();
#pragma unroll 2
        for (int icl = 0; icl < 16; icl++) {
            const float* wr = &ws[icl * 3 * 128];
            u64 w00p[2], w10p[2], w01p[2], w11p[2], w02p[2], w12p[2];
            wsplit(ldf4s(wr + ocq0), w00p);        wsplit(ldf4s(wr + ocq0 + 64), w10p);
            wsplit(ldf4s(wr + 128 + ocq0), w01p);  wsplit(ldf4s(wr + 128 + ocq0 + 64), w11p);
            wsplit(ldf4s(wr + 256 + ocq0), w02p);  wsplit(ldf4s(wr + 256 + ocq0 + 64), w12p);
            float4 xv = ldf4s(&xs[icl * 68 + mq]);
            float xh = xs[icl * 68 + mq + 4];
            u64 xvd[4];
            dup4(xv, xvd);
            u64 xshd[4] = {xvd[1], xvd[2], xvd[3], dup2(xh)};
            rank1p(ae2[0], w01p, xvd);  rank1p(ae2[1], w11p, xvd);    // even: k=1
            rank1p(ao2[0], w00p, xvd);  rank1p(ao2[1], w10p, xvd);    // odd:  k=0
            rank1p(ao2[0], w02p, xshd); rank1p(ao2[1], w12p, xshd);   // odd:  k=2
        }
        __syncthreads();
    }
#pragma unroll
    for (int o = 0; o < 2; o++) {
        float ef[4][4], of_[4][4];
#pragma unroll
        for (int p = 0; p < 2; p++)
#pragma unroll
            for (int j = 0; j < 4; j++) {
                upk2(ae2[o][p][j], ef[2 * p][j], ef[2 * p + 1][j]);
                upk2(ao2[o][p][j], of_[2 * p][j], of_[2 * p + 1][j]);
            }
#pragma unroll
        for (int i = 0; i < 4; i++) {
            int oc = oc0 + ocq0 + o * 64 + i;
            float bv = bias[oc];
            float* base = out + (size_t)(b * 256 + oc) * Tout + 2 * (m0 + mq);
            float4 v0, v1;
            v0.x = ef[i][0] + bv; v0.y = of_[i][0] + bv;
            v0.z = ef[i][1] + bv; v0.w = of_[i][1] + bv;
            v1.x = ef[i][2] + bv; v1.y = of_[i][2] + bv;
            v1.z = ef[i][3] + bv; v1.w = of_[i][3] + bv;
            if (RELU) {
                v0.x = fmaxf(v0.x, 0.f); v0.y = fmaxf(v0.y, 0.f);
                v0.z = fmaxf(v0.z, 0.f); v0.w = fmaxf(v0.w, 0.f);
                v1.x = fmaxf(v1.x, 0.f); v1.y = fmaxf(v1.y, 0.f);
                v1.z = fmaxf(v1.z, 0.f); v1.w = fmaxf(v1.w, 0.f);
            }
            *reinterpret_cast<float4*>(base) = v0;
            *reinterpret_cast<float4*>(base + 4) = v1;
        }
    }
}

// ---------------- VQ: argmax(z.c - 0.5||c||^2), q = codebook[idx] ----------------
__global__ void __launch_bounds__(512)
vq_kernel(const float* __restrict__ z, const float* __restrict__ cbT,
          const float* __restrict__ cnh, const float* __restrict__ cb,
          float* __restrict__ q) {
    __shared__ __align__(16) unsigned long long red[4096];  // 32KB, aliased as cbs
    float* cbs = reinterpret_cast<float*>(red);
    __shared__ __align__(16) float zs[16 * 68];

    const int t0 = blockIdx.x * 64;
    const int b = blockIdx.y;
    const int tid = threadIdx.x;
    const int c_sub = tid & 63, t_sub = tid >> 6;
    const int cq0 = c_sub * 4, tq0 = t_sub * 4;

    u64 acc2[2][2][2][4];  // [code half][t half][code pair][t]
#pragma unroll
    for (int a = 0; a < 2; a++)
#pragma unroll
        for (int qq = 0; qq < 2; qq++)
#pragma unroll
            for (int p = 0; p < 2; p++)
#pragma unroll
                for (int j = 0; j < 4; j++) acc2[a][qq][p][j] = 0ULL;

    for (int k0 = 0; k0 < 64; k0 += 16) {
        for (int i = tid * 4; i < 8192; i += 2048) {
            int row = i >> 9, col = i & 511;
            *reinterpret_cast<float4*>(&cbs[i]) = ldf4s(&cbT[(k0 + row) * 512 + col]);
        }
        if (tid < 256) {
            int i = tid * 4;
            int row = i >> 6, col = i & 63;
            *reinterpret_cast<float4*>(&zs[row * 68 + col]) =
                ldf4s(&z[((size_t)b * 64 + k0 + row) * 2048 + t0 + col]);
        }
        __syncthreads();
#pragma unroll 2
        for (int kl = 0; kl < 16; kl++) {
            u64 cv0p[2], cv1p[2];
            wsplit(ldf4s(&cbs[kl * 512 + cq0]), cv0p);
            wsplit(ldf4s(&cbs[kl * 512 + cq0 + 256]), cv1p);
            float4 zv0 = ldf4s(&zs[kl * 68 + tq0]);
            float4 zv1 = ldf4s(&zs[kl * 68 + tq0 + 32]);
            u64 zv0d[4], zv1d[4];
            dup4(zv0, zv0d); dup4(zv1, zv1d);
            rank1p(acc2[0][0], cv0p, zv0d); rank1p(acc2[0][1], cv0p, zv1d);
            rank1p(acc2[1][0], cv1p, zv0d); rank1p(acc2[1][1], cv1p, zv1d);
        }
        __syncthreads();
    }
    unsigned long long bk[8];
#pragma unroll
    for (int i = 0; i < 8; i++) bk[i] = 0ULL;
#pragma unroll
    for (int cs = 0; cs < 2; cs++)
#pragma unroll
        for (int p = 0; p < 2; p++) {
            int c0 = cq0 + cs * 256 + 2 * p;
            float adj0 = __ldg(&cnh[c0]);
            float adj1 = __ldg(&cnh[c0 + 1]);
#pragma unroll
            for (int ts = 0; ts < 2; ts++)
#pragma unroll
                for (int j = 0; j < 4; j++) {
                    float s0, s1;
                    upk2(acc2[cs][ts][p][j], s0, s1);
                    s0 -= adj0; s1 -= adj1;
                    int tt = ts * 4 + j;
                    unsigned u0 = __float_as_uint(s0);
                    u0 = (u0 & 0x80000000u) ? ~u0 : (u0 | 0x80000000u);
                    unsigned long long key0 =
                        ((unsigned long long)u0 << 32) | (unsigned)(511 - c0);
                    if (key0 > bk[tt]) bk[tt] = key0;
                    unsigned u1 = __float_as_uint(s1);
                    u1 = (u1 & 0x80000000u) ? ~u1 : (u1 | 0x80000000u);
                    unsigned long long key1 =
                        ((unsigned long long)u1 << 32) | (unsigned)(511 - (c0 + 1));
                    if (key1 > bk[tt]) bk[tt] = key1;
                }
        }
#pragma unroll
    for (int ts = 0; ts < 2; ts++)
#pragma unroll
        for (int j = 0; j < 4; j++) {
            int t_loc = tq0 + ts * 32 + j;
            red[t_loc * 64 + c_sub] = bk[ts * 4 + j];
        }
    __syncthreads();
    if (tid < 64) {
        unsigned long long best = 0ULL;
#pragma unroll 8
        for (int m = 0; m < 64; m++) {
            unsigned long long k = red[tid * 64 + m];
            if (k > best) best = k;
        }
        int idx = 511 - (int)(unsigned)(best & 0xffffffffULL);
        const float* crow = cb + (size_t)idx * 64;
        int t = t0 + tid;
        for (int d = 0; d < 64; d++)
            q[((size_t)b * 64 + d) * 2048 + t] = crow[d];
    }
}

// ---------------- launcher ----------------
extern "C" void kernel_launch(void* const* d_in, const int* in_sizes, int n_in,
                              void* d_out, int out_size) {
    (void)in_sizes; (void)n_in; (void)out_size;
    const float* inputs    = (const float*)d_in[0];
    const float* enc_w_in  = (const float*)d_in[1];
    const float* enc_b_in  = (const float*)d_in[2];
    const float* enc_ws    = (const float*)d_in[3];
    const float* enc_bs    = (const float*)d_in[4];
    const float* enc_w_out = (const float*)d_in[5];
    const float* enc_b_out = (const float*)d_in[6];
    const float* codebook  = (const float*)d_in[7];
    const float* dec_w_in  = (const float*)d_in[8];
    const float* dec_b_in  = (const float*)d_in[9];
    const float* dec_ws    = (const float*)d_in[10];
    const float* dec_bs    = (const float*)d_in[11];
    const float* dec_w_out = (const float*)d_in[12];
    const float* dec_b_out = (const float*)d_in[13];
    float* out = (float*)d_out;

    float *bufA, *bufB, *zb, *qb, *wt, *cbT, *cnh;
    cudaGetSymbolAddress((void**)&bufA, g_bufA);
    cudaGetSymbolAddress((void**)&bufB, g_bufB);
    cudaGetSymbolAddress((void**)&zb, g_z);
    cudaGetSymbolAddress((void**)&qb, g_q);
    cudaGetSymbolAddress((void**)&wt, g_wt);
    cudaGetSymbolAddress((void**)&cbT, g_cbT);
    cudaGetSymbolAddress((void**)&cnh, g_cnh);

    const int WSLOT = 768 * 256;  // 196608
    // repack weights
    for (int i = 0; i < 3; i++)
        repack_w_kernel<<<768, 256>>>(enc_ws + (size_t)i * 196608, wt + i * WSLOT, 256, 256);
    repack_w_kernel<<<192, 256>>>(enc_w_out, wt + 3 * WSLOT, 64, 256);
    repack_w_kernel<<<192, 256>>>(dec_w_in, wt + 4 * WSLOT, 256, 64);
    for (int i = 0; i < 3; i++)
        repack_w_kernel<<<768, 256>>>(dec_ws + (size_t)i * 196608, wt + (5 + i) * WSLOT, 256, 256);
    repack_w_kernel<<<768, 256>>>(dec_w_out, wt + 8 * WSLOT, 256, 256);
    cb_prep_kernel<<<1, 512>>>(codebook, cbT, cnh);

    // encoder
    e1_kernel<<<65536, 256>>>(inputs, enc_w_in, enc_b_in, bufA);
    conv_s2_kernel<true><<<dim3(64, 2, 16), 256>>>(bufA, wt + 0 * WSLOT, enc_bs + 0, bufB, 16384, 8192);
    conv_s2_kernel<true><<<dim3(32, 2, 16), 256>>>(bufB, wt + 1 * WSLOT, enc_bs + 256, bufA, 8192, 4096);
    conv_s2_kernel<true><<<dim3(16, 2, 16), 256>>>(bufA, wt + 2 * WSLOT, enc_bs + 512, bufB, 4096, 2048);
    conv_s1_kernel<64, false><<<dim3(16, 1, 16), 128>>>(bufB, wt + 3 * WSLOT, enc_b_out, zb, 2048, 256, 64);

    // VQ
    vq_kernel<<<dim3(32, 16), 512>>>(zb, cbT, cnh, codebook, qb);

    // decoder
    conv_s1_kernel<128, true><<<dim3(16, 2, 16), 256>>>(qb, wt + 4 * WSLOT, dec_b_in, bufA, 2048, 64, 256);
    convT_kernel<true><<<dim3(32, 2, 16), 256>>>(bufA, wt + 5 * WSLOT, dec_bs + 0, bufB, 2048, 4096);
    convT_kernel<true><<<dim3(64, 2, 16), 256>>>(bufB, wt + 6 * WSLOT, dec_bs + 256, bufA, 4096, 8192);
    convT_kernel<true><<<dim3(128, 2, 16), 256>>>(bufA, wt + 7 * WSLOT, dec_bs + 512, bufB, 8192, 16384);
    convT_kernel<false><<<dim3(256, 2, 16), 256>>>(bufB, wt + 8 * WSLOT, dec_b_out, out, 16384, 32768);
}

// round 6
// speedup vs baseline: 2.9195x; 2.7854x over previous
#include <cuda_runtime.h>
#include <cuda_fp16.h>

typedef unsigned long long u64;
typedef unsigned int u32;
#define DI __device__ __forceinline__

#define LO_SCALE 2048.f
#define LO_INV (1.f / 2048.f)

// ---------------- static scratch ----------------
__device__ __half g_h0[16*16384*256];
__device__ __half g_l0[16*16384*256];
__device__ __half g_h1[16*16384*256];
__device__ __half g_l1[16*16384*256];
__device__ float  g_zT[16*2048*64];
__device__ __half g_qh[16*2048*64];
__device__ __half g_ql[16*2048*64];
__device__ __half g_whi[9*196608];
__device__ __half g_wlo[9*196608];
__device__ float  g_cnh[512];

// ---------------- PTX helpers ----------------
DI u32 smem_u32(const void* p) {
    u32 a;
    asm("{ .reg .u64 t; cvta.to.shared.u64 t, %1; cvt.u32.u64 %0, t; }" : "=r"(a) : "l"(p));
    return a;
}
DI void cpa16(u32 dst, const void* src, int src_sz) {
    asm volatile("cp.async.ca.shared.global [%0], [%1], 16, %2;"
                 :: "r"(dst), "l"(src), "r"(src_sz) : "memory");
}
DI void cpa_commit() { asm volatile("cp.async.commit_group;" ::: "memory"); }
DI void cpa_wait1() { asm volatile("cp.async.wait_group 1;" ::: "memory"); }
DI void cpa_wait0() { asm volatile("cp.async.wait_group 0;" ::: "memory"); }
DI void ldsm4(u32* r, u32 addr) {
    asm volatile("ldmatrix.sync.aligned.m8n8.x4.shared.b16 {%0,%1,%2,%3}, [%4];"
                 : "=r"(r[0]), "=r"(r[1]), "=r"(r[2]), "=r"(r[3]) : "r"(addr));
}
DI void mma16816(float* c, const u32* a, u32 b0, u32 b1) {
    asm volatile(
        "mma.sync.aligned.m16n8k16.row.col.f32.f16.f16.f32 "
        "{%0,%1,%2,%3}, {%4,%5,%6,%7}, {%8,%9}, {%0,%1,%2,%3};"
        : "+f"(c[0]), "+f"(c[1]), "+f"(c[2]), "+f"(c[3])
        : "r"(a[0]), "r"(a[1]), "r"(a[2]), "r"(a[3]), "r"(b0), "r"(b1));
}
DI u32 swz(u32 o) { return o ^ ((o >> 3) & 0x70); }

// ---------------- weight repack + split: w[oc][ic][k] -> [(k*nch+c)][oc][64] hi/lo ----------------
__global__ void repack_kernel(const float* __restrict__ w, __half* __restrict__ wh,
                              __half* __restrict__ wl, int OC, int IC) {
    int i = blockIdx.x * 256 + threadIdx.x;
    int n = OC * IC * 3;
    if (i >= n) return;
    int oc = i / (IC * 3);
    int r = i - oc * IC * 3;
    int ic = r / 3, k = r - ic * 3;
    int nch = IC >> 6, c = ic >> 6, j = ic & 63;
    float v = w[i];
    __half h = __float2half_rn(v);
    size_t d = ((size_t)(k * nch + c) * OC + oc) * 64 + j;
    wh[d] = h;
    wl[d] = __float2half_rn((v - __half2float(h)) * LO_SCALE);
}

__global__ void cb_prep_kernel(const float* __restrict__ cb, float* __restrict__ cnh) {
    int c = threadIdx.x;
    float s = 0.f;
    for (int k = 0; k < 64; k++) { float v = cb[c * 64 + k]; s += v * v; }
    cnh[c] = 0.5f * s;
}

// ---------------- encoder layer 1: IC=1, stride 2, relu, t-major hi/lo out ----------------
__global__ void e1_kernel(const float* __restrict__ x, const float* __restrict__ w,
                          const float* __restrict__ bias,
                          __half* __restrict__ oh, __half* __restrict__ ol) {
    __shared__ float xs[132];
    int b = blockIdx.y, tc = blockIdx.x * 64, tid = threadIdx.x;
    const float* xr = x + (size_t)b * 32768;
    for (int i = tid; i < 130; i += 256) {
        int pos = 2 * tc - 1 + i;
        xs[i] = (pos >= 0 && pos < 32768) ? xr[pos] : 0.f;
    }
    __syncthreads();
    float w0 = w[tid * 3], w1 = w[tid * 3 + 1], w2 = w[tid * 3 + 2], bv = bias[tid];
    for (int j = 0; j < 64; j++) {
        float v = fmaxf(bv + w0 * xs[2 * j] + w1 * xs[2 * j + 1] + w2 * xs[2 * j + 2], 0.f);
        __half h = __float2half_rn(v);
        size_t o = ((size_t)b * 16384 + tc + j) * 256 + tid;
        oh[o] = h;
        ol[o] = __float2half_rn((v - __half2float(h)) * LO_SCALE);
    }
}

// ---------------- generic mma.sync conv GEMM (fp16-split, scaled residuals) ----------------
// mode: 0=s1 conv, 1=s2 conv, 2=convT (pair-split), 3=convT final (fp32 ch-major out)
// MTC: 4 -> N=128 (warp tile 64x32), 2 -> N=64 (warp tile 32x32)
template <int MTC>
__global__ void __launch_bounds__(256)
conv_mma_kernel(const __half* __restrict__ in_hi, const __half* __restrict__ in_lo,
                const __half* __restrict__ w_hi, const __half* __restrict__ w_lo,
                const float* __restrict__ bias,
                __half* __restrict__ out_hi, __half* __restrict__ out_lo,
                float* __restrict__ out_f32,
                int IC, int OC, int Tin, int Tout, int mode, int relu) {
    extern __shared__ char smraw[];
    u32 sb0 = smem_u32(smraw);
    u32 sb = (sb0 + 1023) & ~1023u;
    char* smp = smraw + (sb - sb0);

    const int tid = threadIdx.x, lane = tid & 31, wid = tid >> 5;
    const int t0 = blockIdx.x * 128;
    const int N = (MTC == 4) ? 128 : 64;
    int yb = blockIdx.y;
    int oc0, pair;
    if (mode >= 2) { oc0 = (yb & 1) * 128; pair = yb >> 1; }
    else           { oc0 = yb * 128; pair = 0; }
    const int b = blockIdx.z;
    const int nch = IC >> 6;
    const int nsub = (mode < 2) ? 3 * nch : (pair ? 2 * nch : nch);
    const size_t inb = (size_t)b * Tin * IC;

    int wm, wn, mbase;
    if (MTC == 4) { wm = wid & 1; wn = wid >> 1; mbase = wm * 64; }
    else          { wm = wid >> 1; wn = wid & 1; mbase = wm * 32; }

    float acc[MTC][4][4];   // hi*hi
    float accc[MTC][4][4];  // hi*lo + lo*hi (scaled by LO_SCALE)
#pragma unroll
    for (int mt = 0; mt < MTC; mt++)
#pragma unroll
        for (int nt = 0; nt < 4; nt++)
#pragma unroll
            for (int k = 0; k < 4; k++) { acc[mt][nt][k] = 0.f; accc[mt][nt][k] = 0.f; }

    auto geo = [&](int i, int& c, int& kap, int& del) {
        if (mode < 2) { c = i / 3; int s = i - 3 * c; kap = s; del = s - 1; }
        else if (!pair) { c = i; kap = 1; del = 0; }
        else { c = i >> 1; if (i & 1) { kap = 2; del = 1; } else { kap = 0; del = 0; } }
    };
    // stage p: A_hi @ p*65536, A_lo +16384, B_hi +32768, B_lo +49152
    auto load_chunk = [&](int i, int p) {
        int c, kap, del;
        geo(i, c, kap, del);
        u32 abase = sb + p * 65536;
        u32 bbase = abase + 32768;
        int r0 = tid >> 3, qd = tid & 7;
        const __half* sH = in_hi + inb + c * 64 + qd * 8;
        const __half* sL = in_lo + inb + c * 64 + qd * 8;
#pragma unroll
        for (int it = 0; it < 4; it++) {
            int r = r0 + it * 32;
            int g = (mode == 1) ? (2 * (t0 + r) + del) : (t0 + r + del);
            int ok = (g >= 0 && g < Tin) ? 16 : 0;
            int gc = ok ? g : 0;
            u32 so = swz((u32)(r * 128 + qd * 16));
            cpa16(abase + so, sH + (size_t)gc * IC, ok);
            cpa16(abase + 16384 + so, sL + (size_t)gc * IC, ok);
        }
        const __half* wH = w_hi + ((size_t)(kap * nch + c) * OC + oc0) * 64 + qd * 8;
        const __half* wL = w_lo + ((size_t)(kap * nch + c) * OC + oc0) * 64 + qd * 8;
#pragma unroll
        for (int it = 0; it < 4; it++) {
            int r = r0 + it * 32;
            if (r < N) {
                u32 so = swz((u32)(r * 128 + qd * 16));
                cpa16(bbase + so, wH + (size_t)r * 64, 16);
                cpa16(bbase + 16384 + so, wL + (size_t)r * 64, 16);
            }
        }
    };

    load_chunk(0, 0);
    cpa_commit();

    for (int i = 0; i < nsub; i++) {
        int p = i & 1;
        if (i + 1 < nsub) { load_chunk(i + 1, p ^ 1); cpa_commit(); cpa_wait1(); }
        else              { cpa_wait0(); }
        __syncthreads();

        u32 abase = sb + p * 65536;
        u32 bbase = abase + 32768;
#pragma unroll
        for (int ks = 0; ks < 4; ks++) {
            u32 bh[8], bl[8];
#pragma unroll
            for (int q = 0; q < 2; q++) {
                int brow = wn * 32 + q * 16 + ((lane >> 4) & 1) * 8 + (lane & 7);
                int bkb = ks * 32 + ((lane >> 3) & 1) * 16;
                u32 bad = bbase + swz((u32)(brow * 128 + bkb));
                ldsm4(&bh[q * 4], bad);
                ldsm4(&bl[q * 4], bad + 16384);
            }
            int arow = mbase + (lane & 15);
            int akb = ks * 32 + (lane >> 4) * 16;
#pragma unroll
            for (int mt = 0; mt < MTC; mt++) {
                u32 aad = abase + swz((u32)((arow + mt * 16) * 128 + akb));
                u32 ah[4], al[4];
                ldsm4(ah, aad);
                ldsm4(al, aad + 16384);
#pragma unroll
                for (int nt = 0; nt < 4; nt++) {
                    int bi = (nt >> 1) * 4 + (nt & 1) * 2;
                    mma16816(acc[mt][nt], ah, bh[bi], bh[bi + 1]);
                    mma16816(accc[mt][nt], ah, bl[bi], bl[bi + 1]);
                    mma16816(accc[mt][nt], al, bh[bi], bh[bi + 1]);
                }
            }
        }
        __syncthreads();
    }

    // ---------------- epilogue ----------------
    int g = lane >> 2, tg = lane & 3;
    float* stage = reinterpret_cast<float*>(smp);   // mode 3 staging [col][132]
#pragma unroll
    for (int mt = 0; mt < MTC; mt++) {
#pragma unroll
        for (int nt = 0; nt < 4; nt++) {
            int col = wn * 32 + nt * 8 + tg * 2;
            float bv0 = __ldg(bias + oc0 + col);
            float bv1 = __ldg(bias + oc0 + col + 1);
            int r0 = mbase + mt * 16 + g, r1 = r0 + 8;
            float v00 = acc[mt][nt][0] + accc[mt][nt][0] * LO_INV + bv0;
            float v01 = acc[mt][nt][1] + accc[mt][nt][1] * LO_INV + bv1;
            float v10 = acc[mt][nt][2] + accc[mt][nt][2] * LO_INV + bv0;
            float v11 = acc[mt][nt][3] + accc[mt][nt][3] * LO_INV + bv1;
            if (relu) {
                v00 = fmaxf(v00, 0.f); v01 = fmaxf(v01, 0.f);
                v10 = fmaxf(v10, 0.f); v11 = fmaxf(v11, 0.f);
            }
            if (mode == 3) {
                stage[col * 132 + r0] = v00; stage[(col + 1) * 132 + r0] = v01;
                stage[col * 132 + r1] = v10; stage[(col + 1) * 132 + r1] = v11;
            } else if (out_f32 != nullptr) {
                *reinterpret_cast<float2*>(out_f32 + ((size_t)b * Tout + t0 + r0) * OC + oc0 + col) =
                    make_float2(v00, v01);
                *reinterpret_cast<float2*>(out_f32 + ((size_t)b * Tout + t0 + r1) * OC + oc0 + col) =
                    make_float2(v10, v11);
            } else {
                int tr0 = (mode == 2) ? (2 * (t0 + r0) + pair) : (t0 + r0);
                int tr1 = (mode == 2) ? (2 * (t0 + r1) + pair) : (t0 + r1);
                size_t o0 = ((size_t)b * Tout + tr0) * OC + oc0 + col;
                size_t o1 = ((size_t)b * Tout + tr1) * OC + oc0 + col;
                __half h00 = __float2half_rn(v00), h01 = __float2half_rn(v01);
                __half h10 = __float2half_rn(v10), h11 = __float2half_rn(v11);
                *reinterpret_cast<__half2*>(out_hi + o0) = __halves2half2(h00, h01);
                *reinterpret_cast<__half2*>(out_lo + o0) =
                    __halves2half2(__float2half_rn((v00 - __half2float(h00)) * LO_SCALE),
                                   __float2half_rn((v01 - __half2float(h01)) * LO_SCALE));
                *reinterpret_cast<__half2*>(out_hi + o1) = __halves2half2(h10, h11);
                *reinterpret_cast<__half2*>(out_lo + o1) =
                    __halves2half2(__float2half_rn((v10 - __half2float(h10)) * LO_SCALE),
                                   __float2half_rn((v11 - __half2float(h11)) * LO_SCALE));
            }
        }
    }
    if (mode == 3) {
        __syncthreads();
        // stage[col(oc_local)][m] -> out[b][oc0+col][2*(t0+m)+pair]
        for (int q = 0; q < 64; q++) {
            int idx = q * 256 + tid;
            int r = idx >> 7, m = idx & 127;
            out_f32[((size_t)(b * 256 + oc0 + r)) * 32768 + 2 * (t0 + m) + pair] =
                stage[r * 132 + m];
        }
    }
}

// ---------------- VQ: exact fp32 nearest code, q -> hi/lo fp16 ----------------
__global__ void __launch_bounds__(128)
vq_kernel(const float* __restrict__ z, const float* __restrict__ cb,
          const float* __restrict__ cnh,
          __half* __restrict__ qh, __half* __restrict__ ql) {
    extern __shared__ float cbs[];   // [512*64] codebook + [512] cnh
    int tid = threadIdx.x;
    for (int i = tid; i < 512 * 64 / 4; i += 128)
        reinterpret_cast<float4*>(cbs)[i] = reinterpret_cast<const float4*>(cb)[i];
    float* cns = cbs + 512 * 64;
    for (int i = tid; i < 512; i += 128) cns[i] = cnh[i];
    __syncthreads();

    int tg = blockIdx.x * 128 + tid;
    const float* zp = z + (size_t)tg * 64;
    float zr[64];
#pragma unroll
    for (int k = 0; k < 64; k++) zr[k] = zp[k];
    float best = -1e30f;
    int bi = 0;
    for (int c = 0; c < 512; c++) {
        const float* cr = cbs + c * 64;
        float dot = 0.f;
#pragma unroll
        for (int k = 0; k < 64; k++) dot = fmaf(zr[k], cr[k], dot);
        float s = dot - cns[c];
        if (s > best) { best = s; bi = c; }
    }
    const float* cw = cbs + bi * 64;
    __half2* oh = reinterpret_cast<__half2*>(qh + (size_t)tg * 64);
    __half2* ol = reinterpret_cast<__half2*>(ql + (size_t)tg * 64);
#pragma unroll
    for (int k = 0; k < 32; k++) {
        float a0 = cw[2 * k], a1 = cw[2 * k + 1];
        __half h0v = __float2half_rn(a0);
        __half h1v = __float2half_rn(a1);
        oh[k] = __halves2half2(h0v, h1v);
        ol[k] = __halves2half2(__float2half_rn((a0 - __half2float(h0v)) * LO_SCALE),
                               __float2half_rn((a1 - __half2float(h1v)) * LO_SCALE));
    }
}

// ---------------- launcher ----------------
extern "C" void kernel_launch(void* const* d_in, const int* in_sizes, int n_in,
                              void* d_out, int out_size) {
    (void)in_sizes; (void)n_in; (void)out_size;
    const float* inputs    = (const float*)d_in[0];
    const float* enc_w_in  = (const float*)d_in[1];
    const float* enc_b_in  = (const float*)d_in[2];
    const float* enc_ws    = (const float*)d_in[3];
    const float* enc_bs    = (const float*)d_in[4];
    const float* enc_w_out = (const float*)d_in[5];
    const float* enc_b_out = (const float*)d_in[6];
    const float* codebook  = (const float*)d_in[7];
    const float* dec_w_in  = (const float*)d_in[8];
    const float* dec_b_in  = (const float*)d_in[9];
    const float* dec_ws    = (const float*)d_in[10];
    const float* dec_bs    = (const float*)d_in[11];
    const float* dec_w_out = (const float*)d_in[12];
    const float* dec_b_out = (const float*)d_in[13];
    float* out = (float*)d_out;

    __half *h0, *l0, *h1, *l1, *qh, *ql, *wh, *wl;
    float *zT, *cnh;
    cudaGetSymbolAddress((void**)&h0, g_h0);
    cudaGetSymbolAddress((void**)&l0, g_l0);
    cudaGetSymbolAddress((void**)&h1, g_h1);
    cudaGetSymbolAddress((void**)&l1, g_l1);
    cudaGetSymbolAddress((void**)&zT, g_zT);
    cudaGetSymbolAddress((void**)&qh, g_qh);
    cudaGetSymbolAddress((void**)&ql, g_ql);
    cudaGetSymbolAddress((void**)&wh, g_whi);
    cudaGetSymbolAddress((void**)&wl, g_wlo);
    cudaGetSymbolAddress((void**)&cnh, g_cnh);

    const int GEMM_SMEM = 132096;
    const int VQ_SMEM = 512 * 64 * 4 + 512 * 4;
    cudaFuncSetAttribute(conv_mma_kernel<4>, cudaFuncAttributeMaxDynamicSharedMemorySize, GEMM_SMEM);
    cudaFuncSetAttribute(conv_mma_kernel<2>, cudaFuncAttributeMaxDynamicSharedMemorySize, GEMM_SMEM);
    cudaFuncSetAttribute(vq_kernel, cudaFuncAttributeMaxDynamicSharedMemorySize, VQ_SMEM);

    const int WSLOT = 196608;
    for (int i = 0; i < 3; i++)
        repack_kernel<<<768, 256>>>(enc_ws + (size_t)i * 196608, wh + i * WSLOT, wl + i * WSLOT, 256, 256);
    repack_kernel<<<192, 256>>>(enc_w_out, wh + 3 * WSLOT, wl + 3 * WSLOT, 64, 256);
    repack_kernel<<<192, 256>>>(dec_w_in, wh + 4 * WSLOT, wl + 4 * WSLOT, 256, 64);
    for (int i = 0; i < 3; i++)
        repack_kernel<<<768, 256>>>(dec_ws + (size_t)i * 196608, wh + (5 + i) * WSLOT, wl + (5 + i) * WSLOT, 256, 256);
    repack_kernel<<<768, 256>>>(dec_w_out, wh + 8 * WSLOT, wl + 8 * WSLOT, 256, 256);
    cb_prep_kernel<<<1, 512>>>(codebook, cnh);

    // ---- encoder ----
    e1_kernel<<<dim3(256, 16), 256>>>(inputs, enc_w_in, enc_b_in, h0, l0);
    conv_mma_kernel<4><<<dim3(64, 2, 16), 256, GEMM_SMEM>>>(h0, l0, wh + 0 * WSLOT, wl + 0 * WSLOT,
        enc_bs + 0, h1, l1, nullptr, 256, 256, 16384, 8192, 1, 1);
    conv_mma_kernel<4><<<dim3(32, 2, 16), 256, GEMM_SMEM>>>(h1, l1, wh + 1 * WSLOT, wl + 1 * WSLOT,
        enc_bs + 256, h0, l0, nullptr, 256, 256, 8192, 4096, 1, 1);
    conv_mma_kernel<4><<<dim3(16, 2, 16), 256, GEMM_SMEM>>>(h0, l0, wh + 2 * WSLOT, wl + 2 * WSLOT,
        enc_bs + 512, h1, l1, nullptr, 256, 256, 4096, 2048, 1, 1);
    conv_mma_kernel<2><<<dim3(16, 1, 16), 256, GEMM_SMEM>>>(h1, l1, wh + 3 * WSLOT, wl + 3 * WSLOT,
        enc_b_out, nullptr, nullptr, zT, 256, 64, 2048, 2048, 0, 0);

    // ---- VQ ----
    vq_kernel<<<256, 128, VQ_SMEM>>>(zT, codebook, cnh, qh, ql);

    // ---- decoder ----
    conv_mma_kernel<4><<<dim3(16, 2, 16), 256, GEMM_SMEM>>>(qh, ql, wh + 4 * WSLOT, wl + 4 * WSLOT,
        dec_b_in, h0, l0, nullptr, 64, 256, 2048, 2048, 0, 1);
    conv_mma_kernel<4><<<dim3(16, 4, 16), 256, GEMM_SMEM>>>(h0, l0, wh + 5 * WSLOT, wl + 5 * WSLOT,
        dec_bs + 0, h1, l1, nullptr, 256, 256, 2048, 4096, 2, 1);
    conv_mma_kernel<4><<<dim3(32, 4, 16), 256, GEMM_SMEM>>>(h1, l1, wh + 6 * WSLOT, wl + 6 * WSLOT,
        dec_bs + 256, h0, l0, nullptr, 256, 256, 4096, 8192, 2, 1);
    conv_mma_kernel<4><<<dim3(64, 4, 16), 256, GEMM_SMEM>>>(h0, l0, wh + 7 * WSLOT, wl + 7 * WSLOT,
        dec_bs + 512, h1, l1, nullptr, 256, 256, 8192, 16384, 2, 1);
    conv_mma_kernel<4><<<dim3(128, 4, 16), 256, GEMM_SMEM>>>(h1, l1, wh + 8 * WSLOT, wl + 8 * WSLOT,
        dec_b_out, nullptr, nullptr, out, 256, 256, 16384, 32768, 3, 0);
}

// round 7
// speedup vs baseline: 3.1206x; 1.0689x over previous
#include <cuda_runtime.h>
#include <cuda_fp16.h>

typedef unsigned long long u64;
typedef unsigned int u32;
#define DI __device__ __forceinline__

#define LO_SCALE 2048.f
#define LO_INV (1.f / 2048.f)

// ---------------- static scratch ----------------
__device__ __half g_h0[16*16384*256];
__device__ __half g_l0[16*16384*256];
__device__ __half g_h1[16*16384*256];
__device__ __half g_l1[16*16384*256];
__device__ float  g_zT[16*2048*64];
__device__ __half g_qh[16*2048*64];
__device__ __half g_ql[16*2048*64];
__device__ __half g_whi[9*196608];
__device__ __half g_wlo[9*196608];
__device__ float  g_cnh[512];

// ---------------- PTX helpers ----------------
DI u32 smem_u32(const void* p) {
    u32 a;
    asm("{ .reg .u64 t; cvta.to.shared.u64 t, %1; cvt.u32.u64 %0, t; }" : "=r"(a) : "l"(p));
    return a;
}
DI void cpa16(u32 dst, const void* src, int src_sz) {
    asm volatile("cp.async.cg.shared.global [%0], [%1], 16, %2;"
                 :: "r"(dst), "l"(src), "r"(src_sz) : "memory");
}
DI void cpa_commit() { asm volatile("cp.async.commit_group;" ::: "memory"); }
DI void cpa_wait1() { asm volatile("cp.async.wait_group 1;" ::: "memory"); }
DI void cpa_wait0() { asm volatile("cp.async.wait_group 0;" ::: "memory"); }
DI void ldsm4(u32* r, u32 addr) {
    asm volatile("ldmatrix.sync.aligned.m8n8.x4.shared.b16 {%0,%1,%2,%3}, [%4];"
                 : "=r"(r[0]), "=r"(r[1]), "=r"(r[2]), "=r"(r[3]) : "r"(addr));
}
DI void mma16816(float* c, const u32* a, u32 b0, u32 b1) {
    asm volatile(
        "mma.sync.aligned.m16n8k16.row.col.f32.f16.f16.f32 "
        "{%0,%1,%2,%3}, {%4,%5,%6,%7}, {%8,%9}, {%0,%1,%2,%3};"
        : "+f"(c[0]), "+f"(c[1]), "+f"(c[2]), "+f"(c[3])
        : "r"(a[0]), "r"(a[1]), "r"(a[2]), "r"(a[3]), "r"(b0), "r"(b1));
}
DI u32 swz(u32 o) { return o ^ ((o >> 3) & 0x70); }

// ---------------- weight repack + split: w[oc][ic][k] -> [(k*nch+c)][oc][64] hi/lo ----------------
__global__ void repack_kernel(const float* __restrict__ w, __half* __restrict__ wh,
                              __half* __restrict__ wl, int OC, int IC) {
    int i = blockIdx.x * 256 + threadIdx.x;
    int n = OC * IC * 3;
    if (i >= n) return;
    int oc = i / (IC * 3);
    int r = i - oc * IC * 3;
    int ic = r / 3, k = r - ic * 3;
    int nch = IC >> 6, c = ic >> 6, j = ic & 63;
    float v = w[i];
    __half h = __float2half_rn(v);
    size_t d = ((size_t)(k * nch + c) * OC + oc) * 64 + j;
    wh[d] = h;
    wl[d] = __float2half_rn((v - __half2float(h)) * LO_SCALE);
}

__global__ void cb_prep_kernel(const float* __restrict__ cb, float* __restrict__ cnh) {
    int c = threadIdx.x;
    float s = 0.f;
    for (int k = 0; k < 64; k++) { float v = cb[c * 64 + k]; s += v * v; }
    cnh[c] = 0.5f * s;
}

// ---------------- encoder layer 1: IC=1, stride 2, relu, t-major hi/lo out ----------------
__global__ void e1_kernel(const float* __restrict__ x, const float* __restrict__ w,
                          const float* __restrict__ bias,
                          __half* __restrict__ oh, __half* __restrict__ ol) {
    __shared__ float xs[132];
    int b = blockIdx.y, tc = blockIdx.x * 64, tid = threadIdx.x;
    const float* xr = x + (size_t)b * 32768;
    for (int i = tid; i < 130; i += 256) {
        int pos = 2 * tc - 1 + i;
        xs[i] = (pos >= 0 && pos < 32768) ? xr[pos] : 0.f;
    }
    __syncthreads();
    float w0 = w[tid * 3], w1 = w[tid * 3 + 1], w2 = w[tid * 3 + 2], bv = bias[tid];
    for (int j = 0; j < 64; j++) {
        float v = fmaxf(bv + w0 * xs[2 * j] + w1 * xs[2 * j + 1] + w2 * xs[2 * j + 2], 0.f);
        __half h = __float2half_rn(v);
        size_t o = ((size_t)b * 16384 + tc + j) * 256 + tid;
        oh[o] = h;
        ol[o] = __float2half_rn((v - __half2float(h)) * LO_SCALE);
    }
}

// ---------------- generic mma.sync conv GEMM (fp16-split, scaled residuals) ----------------
// mode: 0=s1 conv, 1=s2 conv, 2=convT (pair-split), 3=convT final (fp32 ch-major out)
// MTC: 4 -> N=128 (warp tile 64x32), 2 -> N=64 (warp tile 32x32)
template <int MTC>
__global__ void __launch_bounds__(256)
conv_mma_kernel(const __half* __restrict__ in_hi, const __half* __restrict__ in_lo,
                const __half* __restrict__ w_hi, const __half* __restrict__ w_lo,
                const float* __restrict__ bias,
                __half* __restrict__ out_hi, __half* __restrict__ out_lo,
                float* __restrict__ out_f32,
                int IC, int OC, int Tin, int Tout, int mode, int relu) {
    extern __shared__ char smraw[];
    u32 sb0 = smem_u32(smraw);
    u32 sb = (sb0 + 1023) & ~1023u;
    char* smp = smraw + (sb - sb0);

    const int tid = threadIdx.x, lane = tid & 31, wid = tid >> 5;
    const int t0 = blockIdx.x * 128;
    const int N = (MTC == 4) ? 128 : 64;
    int yb = blockIdx.y;
    int oc0, pair;
    if (mode >= 2) { oc0 = (yb & 1) * 128; pair = yb >> 1; }
    else           { oc0 = yb * 128; pair = 0; }
    const int b = blockIdx.z;
    const int nch = IC >> 6;
    const int nsub = (mode < 2) ? 3 * nch : (pair ? 2 * nch : nch);
    const size_t inb = (size_t)b * Tin * IC;

    int wm, wn, mbase;
    if (MTC == 4) { wm = wid & 1; wn = wid >> 1; mbase = wm * 64; }
    else          { wm = wid >> 1; wn = wid & 1; mbase = wm * 32; }

    float acc[MTC][4][4];   // hi*hi
    float accc[MTC][4][4];  // hi*lo + lo*hi (scaled by LO_SCALE)
#pragma unroll
    for (int mt = 0; mt < MTC; mt++)
#pragma unroll
        for (int nt = 0; nt < 4; nt++)
#pragma unroll
            for (int k = 0; k < 4; k++) { acc[mt][nt][k] = 0.f; accc[mt][nt][k] = 0.f; }

    auto geo = [&](int i, int& c, int& kap, int& del) {
        if (mode < 2) { c = i / 3; int s = i - 3 * c; kap = s; del = s - 1; }
        else if (!pair) { c = i; kap = 1; del = 0; }
        else { c = i >> 1; if (i & 1) { kap = 2; del = 1; } else { kap = 0; del = 0; } }
    };
    // stage p: A_hi @ p*65536, A_lo +16384, B_hi +32768, B_lo +49152
    auto load_chunk = [&](int i, int p) {
        int c, kap, del;
        geo(i, c, kap, del);
        u32 abase = sb + p * 65536;
        u32 bbase = abase + 32768;
        int r0 = tid >> 3, qd = tid & 7;
        const __half* sH = in_hi + inb + c * 64 + qd * 8;
        const __half* sL = in_lo + inb + c * 64 + qd * 8;
#pragma unroll
        for (int it = 0; it < 4; it++) {
            int r = r0 + it * 32;
            int g = (mode == 1) ? (2 * (t0 + r) + del) : (t0 + r + del);
            int ok = (g >= 0 && g < Tin) ? 16 : 0;
            int gc = ok ? g : 0;
            u32 so = swz((u32)(r * 128 + qd * 16));
            cpa16(abase + so, sH + (size_t)gc * IC, ok);
            cpa16(abase + 16384 + so, sL + (size_t)gc * IC, ok);
        }
        const __half* wH = w_hi + ((size_t)(kap * nch + c) * OC + oc0) * 64 + qd * 8;
        const __half* wL = w_lo + ((size_t)(kap * nch + c) * OC + oc0) * 64 + qd * 8;
#pragma unroll
        for (int it = 0; it < 4; it++) {
            int r = r0 + it * 32;
            if (r < N) {
                u32 so = swz((u32)(r * 128 + qd * 16));
                cpa16(bbase + so, wH + (size_t)r * 64, 16);
                cpa16(bbase + 16384 + so, wL + (size_t)r * 64, 16);
            }
        }
    };

    load_chunk(0, 0);
    cpa_commit();

    for (int i = 0; i < nsub; i++) {
        int p = i & 1;
        if (i + 1 < nsub) { load_chunk(i + 1, p ^ 1); cpa_commit(); cpa_wait1(); }
        else              { cpa_wait0(); }
        __syncthreads();

        u32 abase = sb + p * 65536;
        u32 bbase = abase + 32768;
#pragma unroll
        for (int ks = 0; ks < 4; ks++) {
            u32 bh[8], bl[8];
#pragma unroll
            for (int q = 0; q < 2; q++) {
                int brow = wn * 32 + q * 16 + ((lane >> 4) & 1) * 8 + (lane & 7);
                int bkb = ks * 32 + ((lane >> 3) & 1) * 16;
                u32 bad = bbase + swz((u32)(brow * 128 + bkb));
                ldsm4(&bh[q * 4], bad);
                ldsm4(&bl[q * 4], bad + 16384);
            }
            int arow = mbase + (lane & 15);
            int akb = ks * 32 + (lane >> 4) * 16;
            u32 ah[MTC][4], al[MTC][4];
#pragma unroll
            for (int mt = 0; mt < MTC; mt++) {
                u32 aad = abase + swz((u32)((arow + mt * 16) * 128 + akb));
                ldsm4(ah[mt], aad);
                ldsm4(al[mt], aad + 16384);
            }
            // Phase 1: hh into acc  (all independent)
#pragma unroll
            for (int mt = 0; mt < MTC; mt++)
#pragma unroll
                for (int nt = 0; nt < 4; nt++) {
                    int bi = (nt >> 1) * 4 + (nt & 1) * 2;
                    mma16816(acc[mt][nt], ah[mt], bh[bi], bh[bi + 1]);
                }
            // Phase 2: hi*lo into accc (all independent)
#pragma unroll
            for (int mt = 0; mt < MTC; mt++)
#pragma unroll
                for (int nt = 0; nt < 4; nt++) {
                    int bi = (nt >> 1) * 4 + (nt & 1) * 2;
                    mma16816(accc[mt][nt], ah[mt], bl[bi], bl[bi + 1]);
                }
            // Phase 3: lo*hi into accc (RAW vs phase 2 at distance 16 MMAs)
#pragma unroll
            for (int mt = 0; mt < MTC; mt++)
#pragma unroll
                for (int nt = 0; nt < 4; nt++) {
                    int bi = (nt >> 1) * 4 + (nt & 1) * 2;
                    mma16816(accc[mt][nt], al[mt], bh[bi], bh[bi + 1]);
                }
        }
        __syncthreads();
    }

    // ---------------- epilogue ----------------
    int g = lane >> 2, tg = lane & 3;
    float* stage = reinterpret_cast<float*>(smp);   // mode 3 staging [col][132]
#pragma unroll
    for (int mt = 0; mt < MTC; mt++) {
#pragma unroll
        for (int nt = 0; nt < 4; nt++) {
            int col = wn * 32 + nt * 8 + tg * 2;
            float bv0 = __ldg(bias + oc0 + col);
            float bv1 = __ldg(bias + oc0 + col + 1);
            int r0 = mbase + mt * 16 + g, r1 = r0 + 8;
            float v00 = acc[mt][nt][0] + accc[mt][nt][0] * LO_INV + bv0;
            float v01 = acc[mt][nt][1] + accc[mt][nt][1] * LO_INV + bv1;
            float v10 = acc[mt][nt][2] + accc[mt][nt][2] * LO_INV + bv0;
            float v11 = acc[mt][nt][3] + accc[mt][nt][3] * LO_INV + bv1;
            if (relu) {
                v00 = fmaxf(v00, 0.f); v01 = fmaxf(v01, 0.f);
                v10 = fmaxf(v10, 0.f); v11 = fmaxf(v11, 0.f);
            }
            if (mode == 3) {
                stage[col * 132 + r0] = v00; stage[(col + 1) * 132 + r0] = v01;
                stage[col * 132 + r1] = v10; stage[(col + 1) * 132 + r1] = v11;
            } else if (out_f32 != nullptr) {
                *reinterpret_cast<float2*>(out_f32 + ((size_t)b * Tout + t0 + r0) * OC + oc0 + col) =
                    make_float2(v00, v01);
                *reinterpret_cast<float2*>(out_f32 + ((size_t)b * Tout + t0 + r1) * OC + oc0 + col) =
                    make_float2(v10, v11);
            } else {
                int tr0 = (mode == 2) ? (2 * (t0 + r0) + pair) : (t0 + r0);
                int tr1 = (mode == 2) ? (2 * (t0 + r1) + pair) : (t0 + r1);
                size_t o0 = ((size_t)b * Tout + tr0) * OC + oc0 + col;
                size_t o1 = ((size_t)b * Tout + tr1) * OC + oc0 + col;
                __half h00 = __float2half_rn(v00), h01 = __float2half_rn(v01);
                __half h10 = __float2half_rn(v10), h11 = __float2half_rn(v11);
                *reinterpret_cast<__half2*>(out_hi + o0) = __halves2half2(h00, h01);
                *reinterpret_cast<__half2*>(out_lo + o0) =
                    __halves2half2(__float2half_rn((v00 - __half2float(h00)) * LO_SCALE),
                                   __float2half_rn((v01 - __half2float(h01)) * LO_SCALE));
                *reinterpret_cast<__half2*>(out_hi + o1) = __halves2half2(h10, h11);
                *reinterpret_cast<__half2*>(out_lo + o1) =
                    __halves2half2(__float2half_rn((v10 - __half2float(h10)) * LO_SCALE),
                                   __float2half_rn((v11 - __half2float(h11)) * LO_SCALE));
            }
        }
    }
    if (mode == 3) {
        __syncthreads();
        // stage[col(oc_local)][m] -> out[b][oc0+col][2*(t0+m)+pair]
        for (int q = 0; q < 64; q++) {
            int idx = q * 256 + tid;
            int r = idx >> 7, m = idx & 127;
            out_f32[((size_t)(b * 256 + oc0 + r)) * 32768 + 2 * (t0 + m) + pair] =
                stage[r * 132 + m];
        }
    }
}

// ---------------- VQ: exact fp32 nearest code, q -> hi/lo fp16 ----------------
__global__ void __launch_bounds__(128)
vq_kernel(const float* __restrict__ z, const float* __restrict__ cb,
          const float* __restrict__ cnh,
          __half* __restrict__ qh, __half* __restrict__ ql) {
    extern __shared__ float cbs[];   // [512*64] codebook + [512] cnh
    int tid = threadIdx.x;
    for (int i = tid; i < 512 * 64 / 4; i += 128)
        reinterpret_cast<float4*>(cbs)[i] = reinterpret_cast<const float4*>(cb)[i];
    float* cns = cbs + 512 * 64;
    for (int i = tid; i < 512; i += 128) cns[i] = cnh[i];
    __syncthreads();

    int tg = blockIdx.x * 128 + tid;
    const float* zp = z + (size_t)tg * 64;
    float zr[64];
#pragma unroll
    for (int k = 0; k < 64; k++) zr[k] = zp[k];
    float best = -1e30f;
    int bi = 0;
    for (int c = 0; c < 512; c++) {
        const float* cr = cbs + c * 64;
        float dot = 0.f;
#pragma unroll
        for (int k = 0; k < 64; k++) dot = fmaf(zr[k], cr[k], dot);
        float s = dot - cns[c];
        if (s > best) { best = s; bi = c; }
    }
    const float* cw = cbs + bi * 64;
    __half2* oh = reinterpret_cast<__half2*>(qh + (size_t)tg * 64);
    __half2* ol = reinterpret_cast<__half2*>(ql + (size_t)tg * 64);
#pragma unroll
    for (int k = 0; k < 32; k++) {
        float a0 = cw[2 * k], a1 = cw[2 * k + 1];
        __half h0v = __float2half_rn(a0);
        __half h1v = __float2half_rn(a1);
        oh[k] = __halves2half2(h0v, h1v);
        ol[k] = __halves2half2(__float2half_rn((a0 - __half2float(h0v)) * LO_SCALE),
                               __float2half_rn((a1 - __half2float(h1v)) * LO_SCALE));
    }
}

// ---------------- launcher ----------------
extern "C" void kernel_launch(void* const* d_in, const int* in_sizes, int n_in,
                              void* d_out, int out_size) {
    (void)in_sizes; (void)n_in; (void)out_size;
    const float* inputs    = (const float*)d_in[0];
    const float* enc_w_in  = (const float*)d_in[1];
    const float* enc_b_in  = (const float*)d_in[2];
    const float* enc_ws    = (const float*)d_in[3];
    const float* enc_bs    = (const float*)d_in[4];
    const float* enc_w_out = (const float*)d_in[5];
    const float* enc_b_out = (const float*)d_in[6];
    const float* codebook  = (const float*)d_in[7];
    const float* dec_w_in  = (const float*)d_in[8];
    const float* dec_b_in  = (const float*)d_in[9];
    const float* dec_ws    = (const float*)d_in[10];
    const float* dec_bs    = (const float*)d_in[11];
    const float* dec_w_out = (const float*)d_in[12];
    const float* dec_b_out = (const float*)d_in[13];
    float* out = (float*)d_out;

    __half *h0, *l0, *h1, *l1, *qh, *ql, *wh, *wl;
    float *zT, *cnh;
    cudaGetSymbolAddress((void**)&h0, g_h0);
    cudaGetSymbolAddress((void**)&l0, g_l0);
    cudaGetSymbolAddress((void**)&h1, g_h1);
    cudaGetSymbolAddress((void**)&l1, g_l1);
    cudaGetSymbolAddress((void**)&zT, g_zT);
    cudaGetSymbolAddress((void**)&qh, g_qh);
    cudaGetSymbolAddress((void**)&ql, g_ql);
    cudaGetSymbolAddress((void**)&wh, g_whi);
    cudaGetSymbolAddress((void**)&wl, g_wlo);
    cudaGetSymbolAddress((void**)&cnh, g_cnh);

    const int GEMM_SMEM = 132096;
    const int VQ_SMEM = 512 * 64 * 4 + 512 * 4;
    cudaFuncSetAttribute(conv_mma_kernel<4>, cudaFuncAttributeMaxDynamicSharedMemorySize, GEMM_SMEM);
    cudaFuncSetAttribute(conv_mma_kernel<2>, cudaFuncAttributeMaxDynamicSharedMemorySize, GEMM_SMEM);
    cudaFuncSetAttribute(vq_kernel, cudaFuncAttributeMaxDynamicSharedMemorySize, VQ_SMEM);

    const int WSLOT = 196608;
    for (int i = 0; i < 3; i++)
        repack_kernel<<<768, 256>>>(enc_ws + (size_t)i * 196608, wh + i * WSLOT, wl + i * WSLOT, 256, 256);
    repack_kernel<<<192, 256>>>(enc_w_out, wh + 3 * WSLOT, wl + 3 * WSLOT, 64, 256);
    repack_kernel<<<192, 256>>>(dec_w_in, wh + 4 * WSLOT, wl + 4 * WSLOT, 256, 64);
    for (int i = 0; i < 3; i++)
        repack_kernel<<<768, 256>>>(dec_ws + (size_t)i * 196608, wh + (5 + i) * WSLOT, wl + (5 + i) * WSLOT, 256, 256);
    repack_kernel<<<768, 256>>>(dec_w_out, wh + 8 * WSLOT, wl + 8 * WSLOT, 256, 256);
    cb_prep_kernel<<<1, 512>>>(codebook, cnh);

    // ---- encoder ----
    e1_kernel<<<dim3(256, 16), 256>>>(inputs, enc_w_in, enc_b_in, h0, l0);
    conv_mma_kernel<4><<<dim3(64, 2, 16), 256, GEMM_SMEM>>>(h0, l0, wh + 0 * WSLOT, wl + 0 * WSLOT,
        enc_bs + 0, h1, l1, nullptr, 256, 256, 16384, 8192, 1, 1);
    conv_mma_kernel<4><<<dim3(32, 2, 16), 256, GEMM_SMEM>>>(h1, l1, wh + 1 * WSLOT, wl + 1 * WSLOT,
        enc_bs + 256, h0, l0, nullptr, 256, 256, 8192, 4096, 1, 1);
    conv_mma_kernel<4><<<dim3(16, 2, 16), 256, GEMM_SMEM>>>(h0, l0, wh + 2 * WSLOT, wl + 2 * WSLOT,
        enc_bs + 512, h1, l1, nullptr, 256, 256, 4096, 2048, 1, 1);
    conv_mma_kernel<2><<<dim3(16, 1, 16), 256, GEMM_SMEM>>>(h1, l1, wh + 3 * WSLOT, wl + 3 * WSLOT,
        enc_b_out, nullptr, nullptr, zT, 256, 64, 2048, 2048, 0, 0);

    // ---- VQ ----
    vq_kernel<<<256, 128, VQ_SMEM>>>(zT, codebook, cnh, qh, ql);

    // ---- decoder ----
    conv_mma_kernel<4><<<dim3(16, 2, 16), 256, GEMM_SMEM>>>(qh, ql, wh + 4 * WSLOT, wl + 4 * WSLOT,
        dec_b_in, h0, l0, nullptr, 64, 256, 2048, 2048, 0, 1);
    conv_mma_kernel<4><<<dim3(16, 4, 16), 256, GEMM_SMEM>>>(h0, l0, wh + 5 * WSLOT, wl + 5 * WSLOT,
        dec_bs + 0, h1, l1, nullptr, 256, 256, 2048, 4096, 2, 1);
    conv_mma_kernel<4><<<dim3(32, 4, 16), 256, GEMM_SMEM>>>(h1, l1, wh + 6 * WSLOT, wl + 6 * WSLOT,
        dec_bs + 256, h0, l0, nullptr, 256, 256, 4096, 8192, 2, 1);
    conv_mma_kernel<4><<<dim3(64, 4, 16), 256, GEMM_SMEM>>>(h0, l0, wh + 7 * WSLOT, wl + 7 * WSLOT,
        dec_bs + 512, h1, l1, nullptr, 256, 256, 8192, 16384, 2, 1);
    conv_mma_kernel<4><<<dim3(128, 4, 16), 256, GEMM_SMEM>>>(h1, l1, wh + 8 * WSLOT, wl + 8 * WSLOT,
        dec_b_out, nullptr, nullptr, out, 256, 256, 16384, 32768, 3, 0);
}